// round 2
// baseline (speedup 1.0000x reference)
#include <cuda_runtime.h>
#include <math.h>

// ---------------- problem constants ----------------
#define BATCH 2
#define CH    256
#define NH    4
#define DK    64          // CH / NH
#define HW_N  2304        // 48*48
#define C2    512         // 2*CH

#define ESC 0.18033688011112042f   // 0.125 * log2(e)

// ---------------- scratch (device globals; no allocation allowed) ----------
__device__ float g_xs[BATCH*CH*HW_N];
__device__ float g_ys[BATCH*CH*HW_N];
__device__ float g_q [BATCH*CH*HW_N];      // q transposed: [b][n][c]
__device__ float g_k [BATCH*CH*HW_N];      // [b][c][n]
__device__ float g_v [BATCH*CH*HW_N];      // [b][c][n]
__device__ float g_x2[BATCH*CH*HW_N];
__device__ float g_y2[BATCH*CH*HW_N];
__device__ float g_S [(size_t)BATCH*NH*HW_N*HW_N];   // 170 MB scores scratch
__device__ float g_invZ[BATCH*NH*HW_N];
__device__ float g_wt1[CH*CH];             // t1_qw transposed
__device__ float g_wt2[CH*CH];             // t2_qw transposed
__device__ float g_pooled[BATCH*C2];
__device__ float g_sescale[BATCH*C2];      // 1 + sigmoid(f)
__device__ float g_gate[BATCH*2*HW_N];     // 1 + sigmoid(gate)

__device__ __forceinline__ float sigmoidf_(float v){ return 1.f/(1.f+expf(-v)); }

// FMA-pipe exp2 (no MUFU). |rel err| ~4e-5 on the reduced range.
__device__ __forceinline__ float exp2_fast(float x)
{
    x = fminf(fmaxf(x, -60.f), 60.f);
    float m  = x + 12582912.0f;                 // round-to-nearest-int magic
    float rn = m - 12582912.0f;
    float r  = x - rn;
    int   iv = __float_as_int(m) - 0x4B400000;  // integer part
    float p  = 0.0096181291f;
    p = fmaf(p, r, 0.0555041086f);
    p = fmaf(p, r, 0.2402265069f);
    p = fmaf(p, r, 0.6931471806f);
    p = fmaf(p, r, 1.0f);
    return p * __int_as_float((iv + 127) << 23);
}

// ---------------- 1. channel-mean pooling ----------------
__global__ void pool_kernel(const float* __restrict__ x, const float* __restrict__ y)
{
    int idx = blockIdx.x;                 // over BATCH*2C
    int b = idx / C2, ch = idx % C2;
    const float* src = (ch < CH) ? (x + ((long)b*CH + ch)*HW_N)
                                 : (y + ((long)b*CH + (ch-CH))*HW_N);
    float s = 0.f;
    for (int i = threadIdx.x; i < HW_N; i += 256) s += src[i];
    __shared__ float red[256];
    red[threadIdx.x] = s; __syncthreads();
    for (int st = 128; st > 0; st >>= 1) {
        if (threadIdx.x < st) red[threadIdx.x] += red[threadIdx.x+st];
        __syncthreads();
    }
    if (threadIdx.x == 0) g_pooled[idx] = red[0] / (float)HW_N;
}

// ---------------- 2. SE MLP (tiny) ----------------
__global__ void se_kernel(const float* __restrict__ w1, const float* __restrict__ b1,
                          const float* __restrict__ w2, const float* __restrict__ b2)
{
    int b = blockIdx.x, t = threadIdx.x;   // block of 512
    __shared__ float sp[C2], sh[DK];
    sp[t] = g_pooled[b*C2 + t];
    __syncthreads();
    if (t < DK) {
        float s = b1[t];
        for (int c = 0; c < C2; c++) s += w1[t*C2 + c] * sp[c];
        sh[t] = fmaxf(s, 0.f);
    }
    __syncthreads();
    float f = b2[t];
    for (int j = 0; j < DK; j++) f += w2[t*DK + j] * sh[j];
    g_sescale[b*C2 + t] = 1.f + sigmoidf_(f);
}

// ---------------- 3. elementwise SE scale ----------------
__global__ void scale_kernel(const float* __restrict__ x, const float* __restrict__ y)
{
    long i = (long)blockIdx.x*blockDim.x + threadIdx.x;
    if (i >= (long)BATCH*CH*HW_N) return;
    int b = (int)(i / (CH*HW_N));
    int c = (int)((i / HW_N) % CH);
    g_xs[i] = x[i] * g_sescale[b*C2 + c];
    g_ys[i] = y[i] * g_sescale[b*C2 + CH + c];
}

// ---------------- 256x256 weight transpose ----------------
__global__ void transpose256(const float* __restrict__ in, float* __restrict__ out)
{
    __shared__ float tile[32][33];
    int bx = blockIdx.x*32, by = blockIdx.y*32;
    int tx = threadIdx.x, ty = threadIdx.y;  // 32x8
    #pragma unroll
    for (int i = 0; i < 32; i += 8)
        tile[ty+i][tx] = in[(by+ty+i)*CH + bx+tx];
    __syncthreads();
    #pragma unroll
    for (int i = 0; i < 32; i += 8)
        out[(bx+ty+i)*CH + by+tx] = tile[tx][ty+i];
}

// ---------------- generic tiled fp32 GEMM ----------------
// C[M,N] = A*B (+bias).  !TRA: A[m,k] at A[m*lda+k];  TRA: A[m,k] at A[k*lda+m]
// BIAS: 0 none, 1 bias[row], 2 bias[col]
// FEXP: B element b -> exp2_fast(b*ESC) * invZ[z*K + k]  (fused softmax)
template<int BM, int BN, int TM, int TN, bool TRA, int BIAS, bool FEXP>
__global__ void __launch_bounds__(256)
gemm(const float* __restrict__ A, const float* __restrict__ B,
     float* __restrict__ C, const float* __restrict__ bias,
     const float* __restrict__ invZ,
     int K, int lda, int ldb, int ldc,
     int zdiv, long long sA1, long long sA2, long long sB1, long long sB2,
     long long sC1, long long sC2)
{
    constexpr int BK = 16;
    __shared__ float As[2][BK][BM+4];
    __shared__ float Bs[2][BK][BN+4];

    int z  = blockIdx.z;
    int z1 = z / zdiv, z2 = z - z1*zdiv;
    A += z1*sA1 + z2*sA2;
    B += z1*sB1 + z2*sB2;
    C += z1*sC1 + z2*sC2;
    const float* zs = FEXP ? (invZ + (long)z*K) : nullptr;

    int bm = blockIdx.y*BM, bn = blockIdx.x*BN;
    int t  = threadIdx.x;
    int tx = t % (BN/TN), ty = t / (BN/TN);

    constexpr int A_IT = (BK*BM)/(256*4);
    constexpr int B_IT = (BK*BN)/(256*4);
    float4 ra[A_IT], rb[B_IT];

    auto loadA = [&](int k0){
        #pragma unroll
        for (int i = 0; i < A_IT; i++){
            int idx = t + 256*i;
            if (TRA){
                int k = idx/(BM/4), m4 = idx%(BM/4);
                ra[i] = *reinterpret_cast<const float4*>(&A[(long)(k0+k)*lda + bm + m4*4]);
            } else {
                int m = idx/(BK/4), k4 = idx%(BK/4);
                ra[i] = *reinterpret_cast<const float4*>(&A[(long)(bm+m)*lda + k0 + k4*4]);
            }
        }
    };
    auto storeA = [&](int s){
        #pragma unroll
        for (int i = 0; i < A_IT; i++){
            int idx = t + 256*i;
            if (TRA){
                int k = idx/(BM/4), m4 = idx%(BM/4);
                *reinterpret_cast<float4*>(&As[s][k][m4*4]) = ra[i];
            } else {
                int m = idx/(BK/4), k4 = idx%(BK/4);
                As[s][k4*4+0][m] = ra[i].x;
                As[s][k4*4+1][m] = ra[i].y;
                As[s][k4*4+2][m] = ra[i].z;
                As[s][k4*4+3][m] = ra[i].w;
            }
        }
    };
    auto loadB = [&](int k0){
        #pragma unroll
        for (int i = 0; i < B_IT; i++){
            int idx = t + 256*i;
            int k = idx/(BN/4), n4 = idx%(BN/4);
            float4 v = *reinterpret_cast<const float4*>(&B[(long)(k0+k)*ldb + bn + n4*4]);
            if (FEXP){
                float scl = zs[k0+k];
                v.x = exp2_fast(v.x*ESC)*scl;
                v.y = exp2_fast(v.y*ESC)*scl;
                v.z = exp2_fast(v.z*ESC)*scl;
                v.w = exp2_fast(v.w*ESC)*scl;
            }
            rb[i] = v;
        }
    };
    auto storeB = [&](int s){
        #pragma unroll
        for (int i = 0; i < B_IT; i++){
            int idx = t + 256*i;
            int k = idx/(BN/4), n4 = idx%(BN/4);
            *reinterpret_cast<float4*>(&Bs[s][k][n4*4]) = rb[i];
        }
    };

    float acc[TM][TN] = {};

    loadA(0); loadB(0); storeA(0); storeB(0);
    __syncthreads();

    int nT = K/BK;
    for (int tI = 0; tI < nT; tI++){
        int cur = tI & 1, nxt = cur ^ 1;
        if (tI+1 < nT){ loadA((tI+1)*BK); loadB((tI+1)*BK); }
        #pragma unroll
        for (int k = 0; k < BK; k++){
            float a[TM], b[TN];
            #pragma unroll
            for (int i = 0; i < TM/4; i++){
                float4 v = *reinterpret_cast<const float4*>(&As[cur][k][ty*TM + i*4]);
                a[i*4+0]=v.x; a[i*4+1]=v.y; a[i*4+2]=v.z; a[i*4+3]=v.w;
            }
            #pragma unroll
            for (int j = 0; j < TN/4; j++){
                float4 v = *reinterpret_cast<const float4*>(&Bs[cur][k][tx*TN + j*4]);
                b[j*4+0]=v.x; b[j*4+1]=v.y; b[j*4+2]=v.z; b[j*4+3]=v.w;
            }
            #pragma unroll
            for (int i = 0; i < TM; i++)
                #pragma unroll
                for (int j = 0; j < TN; j++)
                    acc[i][j] = fmaf(a[i], b[j], acc[i][j]);
        }
        if (tI+1 < nT){ storeA(nxt); storeB(nxt); }
        __syncthreads();
    }

    float bN[TN];
    #pragma unroll
    for (int j = 0; j < TN; j++)
        bN[j] = (BIAS == 2) ? bias[bn + tx*TN + j] : 0.f;

    #pragma unroll
    for (int i = 0; i < TM; i++){
        long row = bm + ty*TM + i;
        float bM = (BIAS == 1) ? bias[row] : 0.f;
        #pragma unroll
        for (int j = 0; j < TN/4; j++){
            float4 o;
            o.x = acc[i][j*4+0] + bM + bN[j*4+0];
            o.y = acc[i][j*4+1] + bM + bN[j*4+1];
            o.z = acc[i][j*4+2] + bM + bN[j*4+2];
            o.w = acc[i][j*4+3] + bM + bN[j*4+3];
            *reinterpret_cast<float4*>(&C[row*(long)ldc + bn + tx*TN + j*4]) = o;
        }
    }
}

// ---------------- softmax row stats: invZ = 1 / sum_m exp(s*0.125) ----------
__global__ void stats_kernel(const float* __restrict__ S, float* __restrict__ invZ)
{
    long row = blockIdx.x;                 // over B*NH*HW_N rows
    const float4* p = reinterpret_cast<const float4*>(S + row*(long)HW_N);
    float s = 0.f;
    for (int i = threadIdx.x; i < HW_N/4; i += 256){
        float4 v = p[i];
        s += exp2_fast(v.x*ESC) + exp2_fast(v.y*ESC)
           + exp2_fast(v.z*ESC) + exp2_fast(v.w*ESC);
    }
    #pragma unroll
    for (int o = 16; o; o >>= 1) s += __shfl_xor_sync(0xffffffffu, s, o);
    __shared__ float red[8];
    if ((threadIdx.x & 31) == 0) red[threadIdx.x >> 5] = s;
    __syncthreads();
    if (threadIdx.x < 8){
        float v = red[threadIdx.x];
        #pragma unroll
        for (int o = 4; o; o >>= 1) v += __shfl_xor_sync(0xffu, v, o);
        if (threadIdx.x == 0) invZ[row] = 1.0f / v;
    }
}

// ---------------- gating dot products ----------------
__global__ void gate_kernel(const float* __restrict__ gw, const float* __restrict__ gb)
{
    int i = blockIdx.x*blockDim.x + threadIdx.x;   // over BATCH*HW_N
    if (i >= BATCH*HW_N) return;
    int b = i / HW_N, m = i % HW_N;
    const float* xb = g_x2 + (long)b*CH*HW_N + m;
    const float* yb = g_y2 + (long)b*CH*HW_N + m;
    float s0 = gb[0], s1 = gb[1];
    for (int c = 0; c < CH; c++) {
        float xv = xb[(long)c*HW_N];
        s0 = fmaf(gw[c],      xv, s0);
        s1 = fmaf(gw[C2 + c], xv, s1);
    }
    for (int c = 0; c < CH; c++) {
        float yv = yb[(long)c*HW_N];
        s0 = fmaf(gw[CH + c],      yv, s0);
        s1 = fmaf(gw[C2 + CH + c], yv, s1);
    }
    g_gate[b*2*HW_N + m]        = 1.f + sigmoidf_(s0);
    g_gate[b*2*HW_N + HW_N + m] = 1.f + sigmoidf_(s1);
}

// ---------------- final gated writeback ----------------
__global__ void final_kernel(float* __restrict__ out)
{
    long i = (long)blockIdx.x*blockDim.x + threadIdx.x;
    if (i >= (long)BATCH*CH*HW_N) return;
    int b = (int)(i / (CH*HW_N));
    int m = (int)(i % HW_N);
    out[i]                       = g_x2[i] * g_gate[b*2*HW_N + m];
    out[(long)BATCH*CH*HW_N + i] = g_y2[i] * g_gate[b*2*HW_N + HW_N + m];
}

// ---------------- host orchestration ----------------
extern "C" void kernel_launch(void* const* d_in, const int* in_sizes, int n_in,
                              void* d_out, int out_size)
{
    const float* x      = (const float*)d_in[0];
    const float* y      = (const float*)d_in[1];
    const float* fc1w   = (const float*)d_in[2];
    const float* fc1b   = (const float*)d_in[3];
    const float* fc2w   = (const float*)d_in[4];
    const float* fc2b   = (const float*)d_in[5];
    const float* t1_qw  = (const float*)d_in[6];
    const float* t1_qb  = (const float*)d_in[7];
    const float* t1_kw  = (const float*)d_in[8];
    const float* t1_kb  = (const float*)d_in[9];
    const float* t1_vw  = (const float*)d_in[10];
    const float* t1_vb  = (const float*)d_in[11];
    const float* t2_qw  = (const float*)d_in[12];
    const float* t2_qb  = (const float*)d_in[13];
    const float* t2_kw  = (const float*)d_in[14];
    const float* t2_kb  = (const float*)d_in[15];
    const float* t2_vw  = (const float*)d_in[16];
    const float* t2_vb  = (const float*)d_in[17];
    const float* gate_w = (const float*)d_in[18];
    const float* gate_b = (const float*)d_in[19];

    float *xs, *ys, *q, *k, *v, *S, *x2, *y2, *invZ, *wt1, *wt2;
    cudaGetSymbolAddress((void**)&xs,  g_xs);
    cudaGetSymbolAddress((void**)&ys,  g_ys);
    cudaGetSymbolAddress((void**)&q,   g_q);
    cudaGetSymbolAddress((void**)&k,   g_k);
    cudaGetSymbolAddress((void**)&v,   g_v);
    cudaGetSymbolAddress((void**)&S,   g_S);
    cudaGetSymbolAddress((void**)&x2,  g_x2);
    cudaGetSymbolAddress((void**)&y2,  g_y2);
    cudaGetSymbolAddress((void**)&invZ,g_invZ);
    cudaGetSymbolAddress((void**)&wt1, g_wt1);
    cudaGetSymbolAddress((void**)&wt2, g_wt2);

    const long total = (long)BATCH*CH*HW_N;
    const long long NN  = (long long)HW_N*HW_N;
    const long long CN  = (long long)CH*HW_N;
    const long long HN  = (long long)DK*HW_N;

    // --- RScaling ---
    pool_kernel<<<BATCH*C2, 256>>>(x, y);
    se_kernel<<<BATCH, C2>>>(fc1w, fc1b, fc2w, fc2b);
    scale_kernel<<<(int)((total + 255)/256), 256>>>(x, y);

    // pre-transpose q-weights
    transpose256<<<dim3(8,8), dim3(32,8)>>>(t1_qw, wt1);
    transpose256<<<dim3(8,8), dim3(32,8)>>>(t2_qw, wt2);

    auto rtrans = [&](const float* qin, const float* kvin,
                      const float* wtq, const float* qb,
                      const float* kw, const float* kb,
                      const float* vw, const float* vb, float* outp)
    {
        // q_t[b][n][c] = sum_c' qin[b][c'][n] * wtq[c'][c] + qb[c]
        gemm<64,128,4,8,true,2,false><<<dim3(CH/128, HW_N/64, BATCH), 256>>>(
            qin, wtq, q, qb, nullptr,
            CH, HW_N, CH, CH,
            1, CN, 0, 0, 0, CN, 0);
        // k[b][o][m] = sum_c kw[o][c]*kvin[b][c][m] + kb[o]
        gemm<64,128,4,8,false,1,false><<<dim3(HW_N/128, CH/64, BATCH), 256>>>(
            kw, kvin, k, kb, nullptr,
            CH, CH, HW_N, HW_N,
            1, 0, 0, CN, 0, CN, 0);
        gemm<64,128,4,8,false,1,false><<<dim3(HW_N/128, CH/64, BATCH), 256>>>(
            vw, kvin, v, vb, nullptr,
            CH, CH, HW_N, HW_N,
            1, 0, 0, CN, 0, CN, 0);
        // S[z][n][m] = sum_d q_t[b][n][h*64+d] * k[b][h*64+d][m]
        gemm<128,128,8,8,false,0,false><<<dim3(HW_N/128, HW_N/128, BATCH*NH), 256>>>(
            q, k, S, nullptr, nullptr,
            DK, CH, HW_N, HW_N,
            NH, (long long)HW_N*CH, DK, CN, HN, (long long)NH*NN, NN);
        // per-row inverse partition function
        stats_kernel<<<BATCH*NH*HW_N, 256>>>(S, invZ);
        // out[b][h*64+d][m] = sum_n v[b][h*64+d][n] * exp(S[z][n][m]*0.125)*invZ[z][n]
        gemm<64,128,4,8,false,0,true><<<dim3(HW_N/128, 1, BATCH*NH), 256>>>(
            v, S, outp, nullptr, invZ,
            HW_N, HW_N, HW_N, HW_N,
            NH, CN, HN, (long long)NH*NN, NN, CN, HN);
    };

    // RTrans 1: x = attn(q=xs, k=ys, v=ys)
    rtrans(xs, ys, wt1, t1_qb, t1_kw, t1_kb, t1_vw, t1_vb, x2);
    // RTrans 2: y = attn(q=ys, k=x2, v=x2)
    rtrans(ys, x2, wt2, t2_qb, t2_kw, t2_kb, t2_vw, t2_vb, y2);

    // --- RGating + final writeback ---
    gate_kernel<<<(BATCH*HW_N + 255)/256, 256>>>(gate_w, gate_b);
    final_kernel<<<(int)((total + 255)/256), 256>>>((float*)d_out);
}

// round 3
// speedup vs baseline: 2.1779x; 2.1779x over previous
#include <cuda_runtime.h>
#include <math.h>
#include <stdint.h>

// ---------------- problem constants ----------------
#define BATCH 2
#define CH    256
#define NH    4
#define DK    64          // CH / NH
#define HW_N  2304        // 48*48
#define C2    512         // 2*CH

#define ESC 0.18033688011112042f   // 0.125 * log2(e)

// ---------------- scratch (device globals; no allocation allowed) ----------
__device__ float g_xs[BATCH*CH*HW_N];
__device__ float g_ys[BATCH*CH*HW_N];
__device__ float g_q [BATCH*CH*HW_N];      // q transposed: [b][n][c]
__device__ float g_k [BATCH*CH*HW_N];      // [b][c][n]
__device__ float g_v [BATCH*CH*HW_N];      // [b][c][n]
__device__ float g_x2[BATCH*CH*HW_N];
__device__ float g_y2[BATCH*CH*HW_N];
__device__ float g_S [(size_t)BATCH*NH*HW_N*HW_N];   // 170 MB scores scratch (holds E=exp)
__device__ float g_Z [BATCH*NH*HW_N];      // row sums -> inverted in place
__device__ float g_wt1[CH*CH];             // t1_qw transposed
__device__ float g_wt2[CH*CH];             // t2_qw transposed
__device__ float g_pooled[BATCH*C2];
__device__ float g_sescale[BATCH*C2];      // 1 + sigmoid(f)
__device__ float g_gate[BATCH*2*HW_N];     // 1 + sigmoid(gate)

__device__ __forceinline__ float sigmoidf_(float v){ return 1.f/(1.f+expf(-v)); }

// FMA-pipe exp2 (no MUFU). |rel err| ~4e-5 on the reduced range.
__device__ __forceinline__ float exp2_fast(float x)
{
    x = fminf(fmaxf(x, -60.f), 60.f);
    float m  = x + 12582912.0f;                 // round-to-nearest-int magic
    float rn = m - 12582912.0f;
    float r  = x - rn;
    int   iv = __float_as_int(m) - 0x4B400000;  // integer part
    float p  = 0.0096181291f;
    p = fmaf(p, r, 0.0555041086f);
    p = fmaf(p, r, 0.2402265069f);
    p = fmaf(p, r, 0.6931471806f);
    p = fmaf(p, r, 1.0f);
    return p * __int_as_float((iv + 127) << 23);
}

__device__ __forceinline__ float tf32r(float x){
    uint32_t u; asm("cvt.rna.tf32.f32 %0, %1;" : "=r"(u) : "f"(x));
    return __uint_as_float(u);
}

__device__ __forceinline__ void mma_tf32(float (&c)[4], const uint32_t (&a)[4],
                                         const uint32_t (&b)[2])
{
    asm volatile("mma.sync.aligned.m16n8k8.row.col.f32.tf32.tf32.f32 "
        "{%0,%1,%2,%3}, {%4,%5,%6,%7}, {%8,%9}, {%0,%1,%2,%3};"
        : "+f"(c[0]), "+f"(c[1]), "+f"(c[2]), "+f"(c[3])
        : "r"(a[0]), "r"(a[1]), "r"(a[2]), "r"(a[3]), "r"(b[0]), "r"(b[1]));
}

// ---------------- 1. channel-mean pooling ----------------
__global__ void pool_kernel(const float* __restrict__ x, const float* __restrict__ y)
{
    int idx = blockIdx.x;                 // over BATCH*2C
    int b = idx / C2, ch = idx % C2;
    const float* src = (ch < CH) ? (x + ((long)b*CH + ch)*HW_N)
                                 : (y + ((long)b*CH + (ch-CH))*HW_N);
    float s = 0.f;
    for (int i = threadIdx.x; i < HW_N; i += 256) s += src[i];
    __shared__ float red[256];
    red[threadIdx.x] = s; __syncthreads();
    for (int st = 128; st > 0; st >>= 1) {
        if (threadIdx.x < st) red[threadIdx.x] += red[threadIdx.x+st];
        __syncthreads();
    }
    if (threadIdx.x == 0) g_pooled[idx] = red[0] / (float)HW_N;
}

// ---------------- 2. SE MLP (tiny) ----------------
__global__ void se_kernel(const float* __restrict__ w1, const float* __restrict__ b1,
                          const float* __restrict__ w2, const float* __restrict__ b2)
{
    int b = blockIdx.x, t = threadIdx.x;   // block of 512
    __shared__ float sp[C2], sh[DK];
    sp[t] = g_pooled[b*C2 + t];
    __syncthreads();
    if (t < DK) {
        float s = b1[t];
        for (int c = 0; c < C2; c++) s += w1[t*C2 + c] * sp[c];
        sh[t] = fmaxf(s, 0.f);
    }
    __syncthreads();
    float f = b2[t];
    for (int j = 0; j < DK; j++) f += w2[t*DK + j] * sh[j];
    g_sescale[b*C2 + t] = 1.f + sigmoidf_(f);
}

// ---------------- 3. elementwise SE scale ----------------
__global__ void scale_kernel(const float* __restrict__ x, const float* __restrict__ y)
{
    long i = (long)blockIdx.x*blockDim.x + threadIdx.x;
    if (i >= (long)BATCH*CH*HW_N) return;
    int b = (int)(i / (CH*HW_N));
    int c = (int)((i / HW_N) % CH);
    g_xs[i] = x[i] * g_sescale[b*C2 + c];
    g_ys[i] = y[i] * g_sescale[b*C2 + CH + c];
}

// ---------------- 256x256 weight transpose ----------------
__global__ void transpose256(const float* __restrict__ in, float* __restrict__ out)
{
    __shared__ float tile[32][33];
    int bx = blockIdx.x*32, by = blockIdx.y*32;
    int tx = threadIdx.x, ty = threadIdx.y;  // 32x8
    #pragma unroll
    for (int i = 0; i < 32; i += 8)
        tile[ty+i][tx] = in[(by+ty+i)*CH + bx+tx];
    __syncthreads();
    #pragma unroll
    for (int i = 0; i < 32; i += 8)
        out[(bx+ty+i)*CH + by+tx] = tile[tx][ty+i];
}

// ---------------- zero-fill ----------------
__global__ void zfill_kernel(float* __restrict__ p, int n)
{
    int i = blockIdx.x*blockDim.x + threadIdx.x;
    if (i < n) p[i] = 0.f;
}

// ---------------- invert Z in place ----------------
__global__ void zinv_kernel(float* __restrict__ Z, int n)
{
    int i = blockIdx.x*blockDim.x + threadIdx.x;
    if (i < n) Z[i] = 1.0f / Z[i];
}

// ================= TF32 tensor-core GEMM =================
// C[M,N] = A*B (+bias).  !TRA: A[m,k] at A[m*lda+k];  TRA: A[m,k] at A[k*lda+m]
// BIAS: 0 none, 1 bias[row], 2 bias[col]
// EXPZ: C elem -> exp2_fast(c*ESC), plus per-row sums atomically added to Zp[z*M + row]
// BSCALE: B elem scaled by zs[z*K + k] on load
template<int BM, int BN, int WM, int WN, bool TRA, int BIAS, bool EXPZ, bool BSCALE>
__global__ void __launch_bounds__(256)
tgemm(const float* __restrict__ A, const float* __restrict__ B,
      float* __restrict__ C, const float* __restrict__ bias,
      float* __restrict__ Zp, const float* __restrict__ zs_,
      int K, int lda, int ldb, int ldc, int zdiv,
      long long sA1, long long sA2, long long sB1, long long sB2,
      long long sC1, long long sC2)
{
    constexpr int BK = 32;
    constexpr int WCOLS = BN / WN;           // warps along N
    constexpr int MF = WM / 16;
    constexpr int NF = WN / 8;
    constexpr int A_IT = (BM*BK)/(256*4);
    constexpr int B_IT = (BK*BN)/(256*4);

    __shared__ float As[BM][BK+4];
    __shared__ float Bs[BK][BN+4];

    int z  = blockIdx.z;
    int z1 = z / zdiv, z2 = z - z1*zdiv;
    A += z1*sA1 + z2*sA2;
    B += z1*sB1 + z2*sB2;
    C += z1*sC1 + z2*sC2;
    const float* zs = BSCALE ? (zs_ + (long)z*K) : nullptr;

    int bm = blockIdx.y*BM, bn = blockIdx.x*BN;
    int t    = threadIdx.x;
    int warp = t >> 5, lane = t & 31;
    int g = lane >> 2, t4 = lane & 3;
    int wy = warp / WCOLS, wx = warp % WCOLS;

    float4 ra[A_IT], rb[B_IT];

    auto gloadA = [&](int k0){
        #pragma unroll
        for (int i = 0; i < A_IT; i++){
            int idx = t + 256*i;
            if (TRA){
                int k = idx/(BM/4), m4 = idx%(BM/4);
                ra[i] = *reinterpret_cast<const float4*>(&A[(long)(k0+k)*lda + bm + m4*4]);
            } else {
                int m = idx/(BK/4), k4 = idx%(BK/4);
                ra[i] = *reinterpret_cast<const float4*>(&A[(long)(bm+m)*lda + k0 + k4*4]);
            }
        }
    };
    auto gloadB = [&](int k0){
        #pragma unroll
        for (int i = 0; i < B_IT; i++){
            int idx = t + 256*i;
            int k = idx/(BN/4), n4 = idx%(BN/4);
            float4 v = *reinterpret_cast<const float4*>(&B[(long)(k0+k)*ldb + bn + n4*4]);
            if (BSCALE){
                float s = zs[k0+k];
                v.x *= s; v.y *= s; v.z *= s; v.w *= s;
            }
            rb[i] = v;
        }
    };
    auto stsA = [&](){
        #pragma unroll
        for (int i = 0; i < A_IT; i++){
            int idx = t + 256*i;
            if (TRA){
                int k = idx/(BM/4), m4 = idx%(BM/4);
                As[m4*4+0][k] = tf32r(ra[i].x);
                As[m4*4+1][k] = tf32r(ra[i].y);
                As[m4*4+2][k] = tf32r(ra[i].z);
                As[m4*4+3][k] = tf32r(ra[i].w);
            } else {
                int m = idx/(BK/4), k4 = idx%(BK/4);
                float4 v; v.x=tf32r(ra[i].x); v.y=tf32r(ra[i].y);
                          v.z=tf32r(ra[i].z); v.w=tf32r(ra[i].w);
                *reinterpret_cast<float4*>(&As[m][k4*4]) = v;
            }
        }
    };
    auto stsB = [&](){
        #pragma unroll
        for (int i = 0; i < B_IT; i++){
            int idx = t + 256*i;
            int k = idx/(BN/4), n4 = idx%(BN/4);
            float4 v; v.x=tf32r(rb[i].x); v.y=tf32r(rb[i].y);
                      v.z=tf32r(rb[i].z); v.w=tf32r(rb[i].w);
            *reinterpret_cast<float4*>(&Bs[k][n4*4]) = v;
        }
    };

    float acc[MF][NF][4] = {};

    gloadA(0); gloadB(0);
    int nT = K / BK;
    for (int tI = 0; tI < nT; tI++){
        __syncthreads();
        stsA(); stsB();
        __syncthreads();
        if (tI+1 < nT){ gloadA((tI+1)*BK); gloadB((tI+1)*BK); }
        #pragma unroll
        for (int ks = 0; ks < BK/8; ks++){
            uint32_t af[MF][4]; uint32_t bf[NF][2];
            #pragma unroll
            for (int mf = 0; mf < MF; mf++){
                int r = wy*WM + mf*16 + g;
                af[mf][0] = __float_as_uint(As[r    ][ks*8 + t4    ]);
                af[mf][1] = __float_as_uint(As[r + 8][ks*8 + t4    ]);
                af[mf][2] = __float_as_uint(As[r    ][ks*8 + t4 + 4]);
                af[mf][3] = __float_as_uint(As[r + 8][ks*8 + t4 + 4]);
            }
            #pragma unroll
            for (int nf = 0; nf < NF; nf++){
                int cI = wx*WN + nf*8 + g;
                bf[nf][0] = __float_as_uint(Bs[ks*8 + t4    ][cI]);
                bf[nf][1] = __float_as_uint(Bs[ks*8 + t4 + 4][cI]);
            }
            #pragma unroll
            for (int mf = 0; mf < MF; mf++)
                #pragma unroll
                for (int nf = 0; nf < NF; nf++)
                    mma_tf32(acc[mf][nf], af[mf], bf[nf]);
        }
    }

    // ---------------- epilogue ----------------
    long zoff = EXPZ ? (long)z * ((long)gridDim.y * BM) : 0;
    #pragma unroll
    for (int mf = 0; mf < MF; mf++){
        int rbase = bm + wy*WM + mf*16 + g;
        #pragma unroll
        for (int half = 0; half < 2; half++){
            int r = rbase + half*8;
            float bM = (BIAS == 1) ? bias[r] : 0.f;
            float rowsum = 0.f;
            #pragma unroll
            for (int nf = 0; nf < NF; nf++){
                int cI = bn + wx*WN + nf*8 + t4*2;
                float v0 = acc[mf][nf][half*2 + 0];
                float v1 = acc[mf][nf][half*2 + 1];
                if (EXPZ){
                    v0 = exp2_fast(v0*ESC);
                    v1 = exp2_fast(v1*ESC);
                    rowsum += v0 + v1;
                }
                if (BIAS == 1){ v0 += bM; v1 += bM; }
                if (BIAS == 2){ v0 += bias[cI]; v1 += bias[cI+1]; }
                *reinterpret_cast<float2*>(&C[(long)r*ldc + cI]) = make_float2(v0, v1);
            }
            if (EXPZ){
                rowsum += __shfl_xor_sync(0xffffffffu, rowsum, 1);
                rowsum += __shfl_xor_sync(0xffffffffu, rowsum, 2);
                if (t4 == 0) atomicAdd(&Zp[zoff + r], rowsum);
            }
        }
    }
}

// ---------------- gating dot products ----------------
__global__ void gate_kernel(const float* __restrict__ gw, const float* __restrict__ gb)
{
    int i = blockIdx.x*blockDim.x + threadIdx.x;   // over BATCH*HW_N
    if (i >= BATCH*HW_N) return;
    int b = i / HW_N, m = i % HW_N;
    const float* xb = g_x2 + (long)b*CH*HW_N + m;
    const float* yb = g_y2 + (long)b*CH*HW_N + m;
    float s0 = gb[0], s1 = gb[1];
    for (int c = 0; c < CH; c++) {
        float xv = xb[(long)c*HW_N];
        s0 = fmaf(gw[c],      xv, s0);
        s1 = fmaf(gw[C2 + c], xv, s1);
    }
    for (int c = 0; c < CH; c++) {
        float yv = yb[(long)c*HW_N];
        s0 = fmaf(gw[CH + c],      yv, s0);
        s1 = fmaf(gw[C2 + CH + c], yv, s1);
    }
    g_gate[b*2*HW_N + m]        = 1.f + sigmoidf_(s0);
    g_gate[b*2*HW_N + HW_N + m] = 1.f + sigmoidf_(s1);
}

// ---------------- final gated writeback ----------------
__global__ void final_kernel(float* __restrict__ out)
{
    long i = (long)blockIdx.x*blockDim.x + threadIdx.x;
    if (i >= (long)BATCH*CH*HW_N) return;
    int b = (int)(i / (CH*HW_N));
    int m = (int)(i % HW_N);
    out[i]                       = g_x2[i] * g_gate[b*2*HW_N + m];
    out[(long)BATCH*CH*HW_N + i] = g_y2[i] * g_gate[b*2*HW_N + HW_N + m];
}

// ---------------- host orchestration ----------------
extern "C" void kernel_launch(void* const* d_in, const int* in_sizes, int n_in,
                              void* d_out, int out_size)
{
    const float* x      = (const float*)d_in[0];
    const float* y      = (const float*)d_in[1];
    const float* fc1w   = (const float*)d_in[2];
    const float* fc1b   = (const float*)d_in[3];
    const float* fc2w   = (const float*)d_in[4];
    const float* fc2b   = (const float*)d_in[5];
    const float* t1_qw  = (const float*)d_in[6];
    const float* t1_qb  = (const float*)d_in[7];
    const float* t1_kw  = (const float*)d_in[8];
    const float* t1_kb  = (const float*)d_in[9];
    const float* t1_vw  = (const float*)d_in[10];
    const float* t1_vb  = (const float*)d_in[11];
    const float* t2_qw  = (const float*)d_in[12];
    const float* t2_qb  = (const float*)d_in[13];
    const float* t2_kw  = (const float*)d_in[14];
    const float* t2_kb  = (const float*)d_in[15];
    const float* t2_vw  = (const float*)d_in[16];
    const float* t2_vb  = (const float*)d_in[17];
    const float* gate_w = (const float*)d_in[18];
    const float* gate_b = (const float*)d_in[19];

    float *xs, *ys, *q, *k, *v, *S, *x2, *y2, *Z, *wt1, *wt2;
    cudaGetSymbolAddress((void**)&xs,  g_xs);
    cudaGetSymbolAddress((void**)&ys,  g_ys);
    cudaGetSymbolAddress((void**)&q,   g_q);
    cudaGetSymbolAddress((void**)&k,   g_k);
    cudaGetSymbolAddress((void**)&v,   g_v);
    cudaGetSymbolAddress((void**)&S,   g_S);
    cudaGetSymbolAddress((void**)&x2,  g_x2);
    cudaGetSymbolAddress((void**)&y2,  g_y2);
    cudaGetSymbolAddress((void**)&Z,   g_Z);
    cudaGetSymbolAddress((void**)&wt1, g_wt1);
    cudaGetSymbolAddress((void**)&wt2, g_wt2);

    const long total = (long)BATCH*CH*HW_N;
    const long long NN  = (long long)HW_N*HW_N;
    const long long CN  = (long long)CH*HW_N;
    const long long HN  = (long long)DK*HW_N;
    const int ZROWS = BATCH*NH*HW_N;

    // --- RScaling ---
    pool_kernel<<<BATCH*C2, 256>>>(x, y);
    se_kernel<<<BATCH, C2>>>(fc1w, fc1b, fc2w, fc2b);
    scale_kernel<<<(int)((total + 255)/256), 256>>>(x, y);

    // pre-transpose q-weights
    transpose256<<<dim3(8,8), dim3(32,8)>>>(t1_qw, wt1);
    transpose256<<<dim3(8,8), dim3(32,8)>>>(t2_qw, wt2);

    auto rtrans = [&](const float* qin, const float* kvin,
                      const float* wtq, const float* qb,
                      const float* kw, const float* kb,
                      const float* vw, const float* vb, float* outp)
    {
        // q_t[b][n][c] = sum_c' qin[b][c'][n] * wtq[c'][c] + qb[c]
        tgemm<64,128,32,32,true,2,false,false><<<dim3(CH/128, HW_N/64, BATCH), 256>>>(
            qin, wtq, q, qb, nullptr, nullptr,
            CH, HW_N, CH, CH,
            1, CN, 0, 0, 0, CN, 0);
        // k[b][o][m] = sum_c kw[o][c]*kvin[b][c][m] + kb[o]
        tgemm<64,128,32,32,false,1,false,false><<<dim3(HW_N/128, CH/64, BATCH), 256>>>(
            kw, kvin, k, kb, nullptr, nullptr,
            CH, CH, HW_N, HW_N,
            1, 0, 0, CN, 0, CN, 0);
        tgemm<64,128,32,32,false,1,false,false><<<dim3(HW_N/128, CH/64, BATCH), 256>>>(
            vw, kvin, v, vb, nullptr, nullptr,
            CH, CH, HW_N, HW_N,
            1, 0, 0, CN, 0, CN, 0);
        // zero row sums
        zfill_kernel<<<(ZROWS + 255)/256, 256>>>(Z, ZROWS);
        // E[z][n][m] = exp2(S*ESC); Z[z][n] += row sums (atomic)
        tgemm<128,128,64,32,false,0,true,false><<<dim3(HW_N/128, HW_N/128, BATCH*NH), 256>>>(
            q, k, S, nullptr, Z, nullptr,
            DK, CH, HW_N, HW_N,
            NH, (long long)HW_N*CH, DK, CN, HN, (long long)NH*NN, NN);
        // invert row sums
        zinv_kernel<<<(ZROWS + 255)/256, 256>>>(Z, ZROWS);
        // out[b][h*64+d][m] = sum_n v[b][h*64+d][n] * E[z][n][m]*invZ[z][n]
        tgemm<64,128,32,32,false,0,false,true><<<dim3(HW_N/128, 1, BATCH*NH), 256>>>(
            v, S, outp, nullptr, nullptr, Z,
            HW_N, HW_N, HW_N, HW_N,
            NH, CN, HN, (long long)NH*NN, NN, CN, HN);
    };

    // RTrans 1: x = attn(q=xs, k=ys, v=ys)
    rtrans(xs, ys, wt1, t1_qb, t1_kw, t1_kb, t1_vw, t1_vb, x2);
    // RTrans 2: y = attn(q=ys, k=x2, v=x2)
    rtrans(ys, x2, wt2, t2_qb, t2_kw, t2_kb, t2_vw, t2_vb, y2);

    // --- RGating + final writeback ---
    gate_kernel<<<(BATCH*HW_N + 255)/256, 256>>>(gate_w, gate_b);
    final_kernel<<<(int)((total + 255)/256), 256>>>((float*)d_out);
}

// round 4
// speedup vs baseline: 2.6918x; 1.2360x over previous
#include <cuda_runtime.h>
#include <cuda_fp16.h>
#include <math.h>
#include <stdint.h>

// ---------------- problem constants ----------------
#define BATCH 2
#define CH    256
#define NH    4
#define DK    64          // CH / NH
#define HW_N  2304        // 48*48
#define C2    512         // 2*CH

#define ESC 0.18033688011112042f   // 0.125 * log2(e)

// ---------------- scratch (device globals; no allocation allowed) ----------
__device__ float  g_xs[BATCH*CH*HW_N];
__device__ float  g_ys[BATCH*CH*HW_N];
__device__ float  g_q [BATCH*CH*HW_N];      // q transposed: [b][n][c]
__device__ float  g_k [BATCH*CH*HW_N];      // [b][c][n]
__device__ float  g_v [BATCH*CH*HW_N];      // [b][c][n]
__device__ float  g_x2[BATCH*CH*HW_N];
__device__ float  g_y2[BATCH*CH*HW_N];
__device__ __half g_S [(size_t)BATCH*NH*HW_N*HW_N];  // 85 MB: E=exp(S*0.125) in fp16
__device__ float  g_Z [BATCH*NH*HW_N];      // row sums -> inverted in place
__device__ float  g_wt1[CH*CH];             // t1_qw transposed
__device__ float  g_wt2[CH*CH];             // t2_qw transposed
__device__ float  g_pooled[BATCH*C2];
__device__ float  g_sescale[BATCH*C2];      // 1 + sigmoid(f)
__device__ float  g_gate[BATCH*2*HW_N];     // 1 + sigmoid(gate)

__device__ __forceinline__ float sigmoidf_(float v){ return 1.f/(1.f+expf(-v)); }

// FMA-pipe exp2 (no MUFU).
__device__ __forceinline__ float exp2_fast(float x)
{
    x = fminf(fmaxf(x, -60.f), 60.f);
    float m  = x + 12582912.0f;
    float rn = m - 12582912.0f;
    float r  = x - rn;
    int   iv = __float_as_int(m) - 0x4B400000;
    float p  = 0.0096181291f;
    p = fmaf(p, r, 0.0555041086f);
    p = fmaf(p, r, 0.2402265069f);
    p = fmaf(p, r, 0.6931471806f);
    p = fmaf(p, r, 1.0f);
    return p * __int_as_float((iv + 127) << 23);
}

__device__ __forceinline__ uint32_t smaddr(const void* p){
    return (uint32_t)__cvta_generic_to_shared(p);
}
__device__ __forceinline__ void ldm_x4(uint32_t &r0, uint32_t &r1, uint32_t &r2, uint32_t &r3,
                                       uint32_t a){
    asm volatile("ldmatrix.sync.aligned.m8n8.x4.shared.b16 {%0,%1,%2,%3}, [%4];"
        : "=r"(r0),"=r"(r1),"=r"(r2),"=r"(r3) : "r"(a));
}
__device__ __forceinline__ void ldm_x4t(uint32_t &r0, uint32_t &r1, uint32_t &r2, uint32_t &r3,
                                        uint32_t a){
    asm volatile("ldmatrix.sync.aligned.m8n8.x4.trans.shared.b16 {%0,%1,%2,%3}, [%4];"
        : "=r"(r0),"=r"(r1),"=r"(r2),"=r"(r3) : "r"(a));
}
__device__ __forceinline__ void mma_f16(float (&c)[4], const uint32_t (&a)[4],
                                        const uint32_t (&b)[2])
{
    asm volatile("mma.sync.aligned.m16n8k16.row.col.f32.f16.f16.f32 "
        "{%0,%1,%2,%3}, {%4,%5,%6,%7}, {%8,%9}, {%0,%1,%2,%3};"
        : "+f"(c[0]), "+f"(c[1]), "+f"(c[2]), "+f"(c[3])
        : "r"(a[0]), "r"(a[1]), "r"(a[2]), "r"(a[3]), "r"(b[0]), "r"(b[1]));
}

// ---------------- 1. channel-mean pooling ----------------
__global__ void pool_kernel(const float* __restrict__ x, const float* __restrict__ y)
{
    int idx = blockIdx.x;
    int b = idx / C2, ch = idx % C2;
    const float* src = (ch < CH) ? (x + ((long)b*CH + ch)*HW_N)
                                 : (y + ((long)b*CH + (ch-CH))*HW_N);
    float s = 0.f;
    for (int i = threadIdx.x; i < HW_N; i += 256) s += src[i];
    __shared__ float red[256];
    red[threadIdx.x] = s; __syncthreads();
    for (int st = 128; st > 0; st >>= 1) {
        if (threadIdx.x < st) red[threadIdx.x] += red[threadIdx.x+st];
        __syncthreads();
    }
    if (threadIdx.x == 0) g_pooled[idx] = red[0] / (float)HW_N;
}

// ---------------- 2. SE MLP (tiny) ----------------
__global__ void se_kernel(const float* __restrict__ w1, const float* __restrict__ b1,
                          const float* __restrict__ w2, const float* __restrict__ b2)
{
    int b = blockIdx.x, t = threadIdx.x;   // block of 512
    __shared__ float sp[C2], sh[DK];
    sp[t] = g_pooled[b*C2 + t];
    __syncthreads();
    if (t < DK) {
        float s = b1[t];
        for (int c = 0; c < C2; c++) s += w1[t*C2 + c] * sp[c];
        sh[t] = fmaxf(s, 0.f);
    }
    __syncthreads();
    float f = b2[t];
    for (int j = 0; j < DK; j++) f += w2[t*DK + j] * sh[j];
    g_sescale[b*C2 + t] = 1.f + sigmoidf_(f);
}

// ---------------- 3. elementwise SE scale ----------------
__global__ void scale_kernel(const float* __restrict__ x, const float* __restrict__ y)
{
    long i = (long)blockIdx.x*blockDim.x + threadIdx.x;
    if (i >= (long)BATCH*CH*HW_N) return;
    int b = (int)(i / (CH*HW_N));
    int c = (int)((i / HW_N) % CH);
    g_xs[i] = x[i] * g_sescale[b*C2 + c];
    g_ys[i] = y[i] * g_sescale[b*C2 + CH + c];
}

// ---------------- 256x256 weight transpose ----------------
__global__ void transpose256(const float* __restrict__ in, float* __restrict__ out)
{
    __shared__ float tile[32][33];
    int bx = blockIdx.x*32, by = blockIdx.y*32;
    int tx = threadIdx.x, ty = threadIdx.y;
    #pragma unroll
    for (int i = 0; i < 32; i += 8)
        tile[ty+i][tx] = in[(by+ty+i)*CH + bx+tx];
    __syncthreads();
    #pragma unroll
    for (int i = 0; i < 32; i += 8)
        out[(bx+ty+i)*CH + by+tx] = tile[tx][ty+i];
}

__global__ void zfill_kernel(float* __restrict__ p, int n)
{
    int i = blockIdx.x*blockDim.x + threadIdx.x;
    if (i < n) p[i] = 0.f;
}
__global__ void zinv_kernel(float* __restrict__ Z, int n)
{
    int i = blockIdx.x*blockDim.x + threadIdx.x;
    if (i < n) Z[i] = 1.0f / Z[i];
}

// ================= fp16 tensor-core GEMM =================
// C[M,N] = A*B (+bias).  !TRA: A[m,k] at A[m*lda+k];  TRA: A[m,k] at A[k*lda+m]
// BIAS: 0 none, 1 bias[row], 2 bias[col]
// EXPZ: C elem -> half(exp2_fast(c*ESC)); per-row sums atomically added to Zp[z*Mtot+row]
// BHALF: B is __half in gmem, scaled by zs[z*K + k] on load
template<int BM, int BN, int WM, int WN, bool TRA, int BIAS, bool EXPZ, bool BHALF>
__global__ void __launch_bounds__(256)
hgemm(const float* __restrict__ A, const void* __restrict__ Bv,
      void* __restrict__ Cv, const float* __restrict__ bias,
      float* __restrict__ Zp, const float* __restrict__ zs_,
      int K, int lda, int ldb, int ldc, int zdiv,
      long long sA1, long long sA2, long long sB1, long long sB2,
      long long sC1, long long sC2)
{
    constexpr int BK = 32;
    constexpr int WCOLS = BN / WN;
    constexpr int MF = WM / 16;
    constexpr int NF = WN / 8;
    constexpr int PAD = 8;                       // 16B pad
    constexpr int A_IT  = (BM*BK)/(256*4);
    constexpr int BF_IT = (BK*BN)/(256*4);       // float-B float4 count
    constexpr int BH_IT = (BK*BN)/(256*8);       // half-B uint4 count

    __shared__ __half As[2][BM][BK+PAD];
    __shared__ __half Bs[2][BK][BN+PAD];

    int z  = blockIdx.z;
    int z1 = z / zdiv, z2 = z - z1*zdiv;
    A += z1*sA1 + z2*sA2;
    const float*  Bf = BHALF ? nullptr : ((const float*)Bv + z1*sB1 + z2*sB2);
    const __half* Bh = BHALF ? ((const __half*)Bv + z1*sB1 + z2*sB2) : nullptr;
    float*  Cf = EXPZ ? nullptr : ((float*)Cv + z1*sC1 + z2*sC2);
    __half* Ch = EXPZ ? ((__half*)Cv + z1*sC1 + z2*sC2) : nullptr;
    const float* zs = BHALF ? (zs_ + (long)z*K) : nullptr;

    int bm = blockIdx.y*BM, bn = blockIdx.x*BN;
    int t    = threadIdx.x;
    int warp = t >> 5, lane = t & 31;
    int g = lane >> 2, t4 = lane & 3;
    int wy = warp / WCOLS, wx = warp % WCOLS;

    float4 ra[A_IT];
    float4 rbf[BHALF ? 1 : BF_IT];
    uint4  rbh[BHALF ? BH_IT : 1];
    float  rbsc[BHALF ? BH_IT : 1];

    auto gloadA = [&](int k0){
        #pragma unroll
        for (int i = 0; i < A_IT; i++){
            int idx = t + 256*i;
            if (TRA){
                int k = idx/(BM/4), m4 = idx%(BM/4);
                ra[i] = *reinterpret_cast<const float4*>(&A[(long)(k0+k)*lda + bm + m4*4]);
            } else {
                int m = idx/(BK/4), k4 = idx%(BK/4);
                ra[i] = *reinterpret_cast<const float4*>(&A[(long)(bm+m)*lda + k0 + k4*4]);
            }
        }
    };
    auto gloadB = [&](int k0){
        if (BHALF){
            #pragma unroll
            for (int i = 0; i < BH_IT; i++){
                int idx = t + 256*i;
                int k = idx/(BN/8), n8 = idx%(BN/8);
                rbh[i]  = *reinterpret_cast<const uint4*>(&Bh[(long)(k0+k)*ldb + bn + n8*8]);
                rbsc[i] = zs[k0+k];
            }
        } else {
            #pragma unroll
            for (int i = 0; i < BF_IT; i++){
                int idx = t + 256*i;
                int k = idx/(BN/4), n4 = idx%(BN/4);
                rbf[i] = *reinterpret_cast<const float4*>(&Bf[(long)(k0+k)*ldb + bn + n4*4]);
            }
        }
    };
    auto stsA = [&](int s){
        #pragma unroll
        for (int i = 0; i < A_IT; i++){
            int idx = t + 256*i;
            if (TRA){
                int k = idx/(BM/4), m4 = idx%(BM/4);
                As[s][m4*4+0][k] = __float2half_rn(ra[i].x);
                As[s][m4*4+1][k] = __float2half_rn(ra[i].y);
                As[s][m4*4+2][k] = __float2half_rn(ra[i].z);
                As[s][m4*4+3][k] = __float2half_rn(ra[i].w);
            } else {
                int m = idx/(BK/4), k4 = idx%(BK/4);
                __half2 h01 = __floats2half2_rn(ra[i].x, ra[i].y);
                __half2 h23 = __floats2half2_rn(ra[i].z, ra[i].w);
                *reinterpret_cast<__half2*>(&As[s][m][k4*4  ]) = h01;
                *reinterpret_cast<__half2*>(&As[s][m][k4*4+2]) = h23;
            }
        }
    };
    auto stsB = [&](int s){
        if (BHALF){
            #pragma unroll
            for (int i = 0; i < BH_IT; i++){
                int idx = t + 256*i;
                int k = idx/(BN/8), n8 = idx%(BN/8);
                const __half2* hp = reinterpret_cast<const __half2*>(&rbh[i]);
                float sc = rbsc[i];
                __half2 o[4];
                #pragma unroll
                for (int j = 0; j < 4; j++){
                    float2 f = __half22float2(hp[j]);
                    o[j] = __floats2half2_rn(f.x*sc, f.y*sc);
                }
                *reinterpret_cast<uint4*>(&Bs[s][k][n8*8]) = *reinterpret_cast<uint4*>(o);
            }
        } else {
            #pragma unroll
            for (int i = 0; i < BF_IT; i++){
                int idx = t + 256*i;
                int k = idx/(BN/4), n4 = idx%(BN/4);
                __half2 h01 = __floats2half2_rn(rbf[i].x, rbf[i].y);
                __half2 h23 = __floats2half2_rn(rbf[i].z, rbf[i].w);
                *reinterpret_cast<__half2*>(&Bs[s][k][n4*4  ]) = h01;
                *reinterpret_cast<__half2*>(&Bs[s][k][n4*4+2]) = h23;
            }
        }
    };

    float acc[MF][NF][4] = {};

    gloadA(0); gloadB(0);
    stsA(0); stsB(0);
    __syncthreads();

    int nT = K / BK;
    for (int tI = 0; tI < nT; tI++){
        int cur = tI & 1, nxt = cur ^ 1;
        if (tI+1 < nT){ gloadA((tI+1)*BK); gloadB((tI+1)*BK); }

        int arow = wy*WM + (lane & 15);
        int acol = (lane >> 4) << 3;
        #pragma unroll
        for (int kc = 0; kc < BK/16; kc++){
            uint32_t af[MF][4]; uint32_t bf[NF][2];
            #pragma unroll
            for (int mf = 0; mf < MF; mf++){
                uint32_t a = smaddr(&As[cur][arow + mf*16][kc*16 + acol]);
                ldm_x4(af[mf][0], af[mf][1], af[mf][2], af[mf][3], a);
            }
            #pragma unroll
            for (int nf2 = 0; nf2 < NF/2; nf2++){
                uint32_t a = smaddr(&Bs[cur][kc*16 + (lane & 15)]
                                            [wx*WN + nf2*16 + ((lane >> 4) << 3)]);
                ldm_x4t(bf[nf2*2][0], bf[nf2*2][1], bf[nf2*2+1][0], bf[nf2*2+1][1], a);
            }
            #pragma unroll
            for (int mf = 0; mf < MF; mf++)
                #pragma unroll
                for (int nf = 0; nf < NF; nf++)
                    mma_f16(acc[mf][nf], af[mf], bf[nf]);
        }
        if (tI+1 < nT){ stsA(nxt); stsB(nxt); __syncthreads(); }
    }

    // ---------------- epilogue ----------------
    long zoff = EXPZ ? (long)z * ((long)gridDim.y * BM) : 0;
    #pragma unroll
    for (int mf = 0; mf < MF; mf++){
        int rbase = bm + wy*WM + mf*16 + g;
        #pragma unroll
        for (int half = 0; half < 2; half++){
            int r = rbase + half*8;
            float bM = (BIAS == 1) ? bias[r] : 0.f;
            float rowsum = 0.f;
            #pragma unroll
            for (int nf = 0; nf < NF; nf++){
                int cI = bn + wx*WN + nf*8 + t4*2;
                float v0 = acc[mf][nf][half*2 + 0];
                float v1 = acc[mf][nf][half*2 + 1];
                if (EXPZ){
                    v0 = exp2_fast(v0*ESC);
                    v1 = exp2_fast(v1*ESC);
                    rowsum += v0 + v1;
                    *reinterpret_cast<__half2*>(&Ch[(long)r*ldc + cI]) =
                        __floats2half2_rn(v0, v1);
                } else {
                    if (BIAS == 1){ v0 += bM; v1 += bM; }
                    if (BIAS == 2){ v0 += bias[cI]; v1 += bias[cI+1]; }
                    *reinterpret_cast<float2*>(&Cf[(long)r*ldc + cI]) = make_float2(v0, v1);
                }
            }
            if (EXPZ){
                rowsum += __shfl_xor_sync(0xffffffffu, rowsum, 1);
                rowsum += __shfl_xor_sync(0xffffffffu, rowsum, 2);
                if (t4 == 0) atomicAdd(&Zp[zoff + r], rowsum);
            }
        }
    }
}

// ---------------- gating dot products ----------------
__global__ void gate_kernel(const float* __restrict__ gw, const float* __restrict__ gb)
{
    int i = blockIdx.x*blockDim.x + threadIdx.x;
    if (i >= BATCH*HW_N) return;
    int b = i / HW_N, m = i % HW_N;
    const float* xb = g_x2 + (long)b*CH*HW_N + m;
    const float* yb = g_y2 + (long)b*CH*HW_N + m;
    float s0 = gb[0], s1 = gb[1];
    for (int c = 0; c < CH; c++) {
        float xv = xb[(long)c*HW_N];
        s0 = fmaf(gw[c],      xv, s0);
        s1 = fmaf(gw[C2 + c], xv, s1);
    }
    for (int c = 0; c < CH; c++) {
        float yv = yb[(long)c*HW_N];
        s0 = fmaf(gw[CH + c],      yv, s0);
        s1 = fmaf(gw[C2 + CH + c], yv, s1);
    }
    g_gate[b*2*HW_N + m]        = 1.f + sigmoidf_(s0);
    g_gate[b*2*HW_N + HW_N + m] = 1.f + sigmoidf_(s1);
}

// ---------------- final gated writeback ----------------
__global__ void final_kernel(float* __restrict__ out)
{
    long i = (long)blockIdx.x*blockDim.x + threadIdx.x;
    if (i >= (long)BATCH*CH*HW_N) return;
    int b = (int)(i / (CH*HW_N));
    int m = (int)(i % HW_N);
    out[i]                       = g_x2[i] * g_gate[b*2*HW_N + m];
    out[(long)BATCH*CH*HW_N + i] = g_y2[i] * g_gate[b*2*HW_N + HW_N + m];
}

// ---------------- host orchestration ----------------
extern "C" void kernel_launch(void* const* d_in, const int* in_sizes, int n_in,
                              void* d_out, int out_size)
{
    const float* x      = (const float*)d_in[0];
    const float* y      = (const float*)d_in[1];
    const float* fc1w   = (const float*)d_in[2];
    const float* fc1b   = (const float*)d_in[3];
    const float* fc2w   = (const float*)d_in[4];
    const float* fc2b   = (const float*)d_in[5];
    const float* t1_qw  = (const float*)d_in[6];
    const float* t1_qb  = (const float*)d_in[7];
    const float* t1_kw  = (const float*)d_in[8];
    const float* t1_kb  = (const float*)d_in[9];
    const float* t1_vw  = (const float*)d_in[10];
    const float* t1_vb  = (const float*)d_in[11];
    const float* t2_qw  = (const float*)d_in[12];
    const float* t2_qb  = (const float*)d_in[13];
    const float* t2_kw  = (const float*)d_in[14];
    const float* t2_kb  = (const float*)d_in[15];
    const float* t2_vw  = (const float*)d_in[16];
    const float* t2_vb  = (const float*)d_in[17];
    const float* gate_w = (const float*)d_in[18];
    const float* gate_b = (const float*)d_in[19];

    float *xs, *ys, *q, *k, *v, *x2, *y2, *Z, *wt1, *wt2;
    __half *S;
    cudaGetSymbolAddress((void**)&xs,  g_xs);
    cudaGetSymbolAddress((void**)&ys,  g_ys);
    cudaGetSymbolAddress((void**)&q,   g_q);
    cudaGetSymbolAddress((void**)&k,   g_k);
    cudaGetSymbolAddress((void**)&v,   g_v);
    cudaGetSymbolAddress((void**)&S,   g_S);
    cudaGetSymbolAddress((void**)&x2,  g_x2);
    cudaGetSymbolAddress((void**)&y2,  g_y2);
    cudaGetSymbolAddress((void**)&Z,   g_Z);
    cudaGetSymbolAddress((void**)&wt1, g_wt1);
    cudaGetSymbolAddress((void**)&wt2, g_wt2);

    const long total = (long)BATCH*CH*HW_N;
    const long long NN  = (long long)HW_N*HW_N;
    const long long CN  = (long long)CH*HW_N;
    const long long HN  = (long long)DK*HW_N;
    const int ZROWS = BATCH*NH*HW_N;

    // --- RScaling ---
    pool_kernel<<<BATCH*C2, 256>>>(x, y);
    se_kernel<<<BATCH, C2>>>(fc1w, fc1b, fc2w, fc2b);
    scale_kernel<<<(int)((total + 255)/256), 256>>>(x, y);

    transpose256<<<dim3(8,8), dim3(32,8)>>>(t1_qw, wt1);
    transpose256<<<dim3(8,8), dim3(32,8)>>>(t2_qw, wt2);

    auto rtrans = [&](const float* qin, const float* kvin,
                      const float* wtq, const float* qb,
                      const float* kw, const float* kb,
                      const float* vw, const float* vb, float* outp)
    {
        // q_t[b][n][c] = sum_c' qin[b][c'][n] * wtq[c'][c] + qb[c]
        hgemm<128,128,64,32,true,2,false,false><<<dim3(CH/128, HW_N/128, BATCH), 256>>>(
            qin, wtq, q, qb, nullptr, nullptr,
            CH, HW_N, CH, CH,
            1, CN, 0, 0, 0, CN, 0);
        // k[b][o][m] = sum_c kw[o][c]*kvin[b][c][m] + kb[o]
        hgemm<128,128,64,32,false,1,false,false><<<dim3(HW_N/128, CH/128, BATCH), 256>>>(
            kw, kvin, k, kb, nullptr, nullptr,
            CH, CH, HW_N, HW_N,
            1, 0, 0, CN, 0, CN, 0);
        hgemm<128,128,64,32,false,1,false,false><<<dim3(HW_N/128, CH/128, BATCH), 256>>>(
            vw, kvin, v, vb, nullptr, nullptr,
            CH, CH, HW_N, HW_N,
            1, 0, 0, CN, 0, CN, 0);
        // zero row sums
        zfill_kernel<<<(ZROWS + 255)/256, 256>>>(Z, ZROWS);
        // E[z][n][m] = half(exp2(S*ESC)); Z[z][n] += row sums (atomic)
        hgemm<128,128,64,32,false,0,true,false><<<dim3(HW_N/128, HW_N/128, BATCH*NH), 256>>>(
            q, k, S, nullptr, Z, nullptr,
            DK, CH, HW_N, HW_N,
            NH, (long long)HW_N*CH, DK, CN, HN, (long long)NH*NN, NN);
        zinv_kernel<<<(ZROWS + 255)/256, 256>>>(Z, ZROWS);
        // out[b][h*64+d][m] = sum_n v[b][h*64+d][n] * (E[z][n][m]*invZ[z][n])
        hgemm<64,128,32,32,false,0,false,true><<<dim3(HW_N/128, 1, BATCH*NH), 256>>>(
            v, S, outp, nullptr, nullptr, Z,
            HW_N, HW_N, HW_N, HW_N,
            NH, CN, HN, (long long)NH*NN, NN, CN, HN);
    };

    // RTrans 1: x = attn(q=xs, k=ys, v=ys)
    rtrans(xs, ys, wt1, t1_qb, t1_kw, t1_kb, t1_vw, t1_vb, x2);
    // RTrans 2: y = attn(q=ys, k=x2, v=x2)
    rtrans(ys, x2, wt2, t2_qb, t2_kw, t2_kb, t2_vw, t2_vb, y2);

    // --- RGating + final writeback ---
    gate_kernel<<<(BATCH*HW_N + 255)/256, 256>>>(gate_w, gate_b);
    final_kernel<<<(int)((total + 255)/256), 256>>>((float*)d_out);
}

// round 5
// speedup vs baseline: 3.4574x; 1.2844x over previous
#include <cuda_runtime.h>
#include <cuda_fp16.h>
#include <math.h>
#include <stdint.h>

// ---------------- problem constants ----------------
#define BATCH 2
#define CH    256
#define NH    4
#define DK    64          // CH / NH
#define HW_N  2304        // 48*48
#define C2    512         // 2*CH

#define ESC 0.18033688011112042f   // 0.125 * log2(e)

// ---------------- scratch (device globals; no allocation allowed) ----------
__device__ float  g_xs[BATCH*CH*HW_N];
__device__ float  g_ys[BATCH*CH*HW_N];
__device__ __half g_q [BATCH*CH*HW_N];      // q transposed: [b][n][c]  (half)
__device__ __half g_k [BATCH*CH*HW_N];      // [b][c][n] (half)
__device__ __half g_v [BATCH*CH*HW_N];      // [b][c][n] (half)
__device__ float  g_x2[BATCH*CH*HW_N];
__device__ float  g_y2[BATCH*CH*HW_N];
__device__ __half g_S [(size_t)BATCH*NH*HW_N*HW_N];  // 85 MB: E=exp(S*0.125) fp16
__device__ float  g_Z [BATCH*NH*HW_N];      // row sums -> inverted in place
__device__ float  g_wt1[CH*CH];             // t1_qw transposed
__device__ float  g_wt2[CH*CH];             // t2_qw transposed
__device__ float  g_pooled[BATCH*C2];
__device__ float  g_sescale[BATCH*C2];      // 1 + sigmoid(f)
__device__ float  g_gate[BATCH*2*HW_N];     // 1 + sigmoid(gate)

__device__ __forceinline__ float sigmoidf_(float v){ return 1.f/(1.f+expf(-v)); }

// FMA-pipe exp2 (no MUFU).
__device__ __forceinline__ float exp2_fast(float x)
{
    x = fminf(fmaxf(x, -60.f), 60.f);
    float m  = x + 12582912.0f;
    float rn = m - 12582912.0f;
    float r  = x - rn;
    int   iv = __float_as_int(m) - 0x4B400000;
    float p  = 0.0096181291f;
    p = fmaf(p, r, 0.0555041086f);
    p = fmaf(p, r, 0.2402265069f);
    p = fmaf(p, r, 0.6931471806f);
    p = fmaf(p, r, 1.0f);
    return p * __int_as_float((iv + 127) << 23);
}

__device__ __forceinline__ uint32_t smaddr(const void* p){
    return (uint32_t)__cvta_generic_to_shared(p);
}
__device__ __forceinline__ void ldm_x4(uint32_t &r0, uint32_t &r1, uint32_t &r2, uint32_t &r3,
                                       uint32_t a){
    asm volatile("ldmatrix.sync.aligned.m8n8.x4.shared.b16 {%0,%1,%2,%3}, [%4];"
        : "=r"(r0),"=r"(r1),"=r"(r2),"=r"(r3) : "r"(a));
}
__device__ __forceinline__ void ldm_x4t(uint32_t &r0, uint32_t &r1, uint32_t &r2, uint32_t &r3,
                                        uint32_t a){
    asm volatile("ldmatrix.sync.aligned.m8n8.x4.trans.shared.b16 {%0,%1,%2,%3}, [%4];"
        : "=r"(r0),"=r"(r1),"=r"(r2),"=r"(r3) : "r"(a));
}
__device__ __forceinline__ void mma_f16(float (&c)[4], const uint32_t (&a)[4],
                                        const uint32_t (&b)[2])
{
    asm volatile("mma.sync.aligned.m16n8k16.row.col.f32.f16.f16.f32 "
        "{%0,%1,%2,%3}, {%4,%5,%6,%7}, {%8,%9}, {%0,%1,%2,%3};"
        : "+f"(c[0]), "+f"(c[1]), "+f"(c[2]), "+f"(c[3])
        : "r"(a[0]), "r"(a[1]), "r"(a[2]), "r"(a[3]), "r"(b[0]), "r"(b[1]));
}

// ---------------- channel-mean pooling ----------------
__global__ void pool_kernel(const float* __restrict__ x, const float* __restrict__ y)
{
    int idx = blockIdx.x;
    int b = idx / C2, ch = idx % C2;
    const float* src = (ch < CH) ? (x + ((long)b*CH + ch)*HW_N)
                                 : (y + ((long)b*CH + (ch-CH))*HW_N);
    float s = 0.f;
    for (int i = threadIdx.x; i < HW_N; i += 256) s += src[i];
    __shared__ float red[256];
    red[threadIdx.x] = s; __syncthreads();
    for (int st = 128; st > 0; st >>= 1) {
        if (threadIdx.x < st) red[threadIdx.x] += red[threadIdx.x+st];
        __syncthreads();
    }
    if (threadIdx.x == 0) g_pooled[idx] = red[0] / (float)HW_N;
}

// ---------------- SE MLP ----------------
__global__ void se_kernel(const float* __restrict__ w1, const float* __restrict__ b1,
                          const float* __restrict__ w2, const float* __restrict__ b2)
{
    int b = blockIdx.x, t = threadIdx.x;   // block of 512
    __shared__ float sp[C2], sh[DK];
    sp[t] = g_pooled[b*C2 + t];
    __syncthreads();
    if (t < DK) {
        float s = b1[t];
        for (int c = 0; c < C2; c++) s += w1[t*C2 + c] * sp[c];
        sh[t] = fmaxf(s, 0.f);
    }
    __syncthreads();
    float f = b2[t];
    for (int j = 0; j < DK; j++) f += w2[t*DK + j] * sh[j];
    g_sescale[b*C2 + t] = 1.f + sigmoidf_(f);
}

// ---------------- elementwise SE scale ----------------
__global__ void scale_kernel(const float* __restrict__ x, const float* __restrict__ y)
{
    long i = (long)blockIdx.x*blockDim.x + threadIdx.x;
    if (i >= (long)BATCH*CH*HW_N) return;
    int b = (int)(i / (CH*HW_N));
    int c = (int)((i / HW_N) % CH);
    g_xs[i] = x[i] * g_sescale[b*C2 + c];
    g_ys[i] = y[i] * g_sescale[b*C2 + CH + c];
}

// ---------------- fused double 256x256 weight transpose ----------------
__global__ void transpose256x2(const float* __restrict__ in0, float* __restrict__ out0,
                               const float* __restrict__ in1, float* __restrict__ out1)
{
    const float* in  = blockIdx.z ? in1  : in0;
    float*       out = blockIdx.z ? out1 : out0;
    __shared__ float tile[32][33];
    int bx = blockIdx.x*32, by = blockIdx.y*32;
    int tx = threadIdx.x, ty = threadIdx.y;
    #pragma unroll
    for (int i = 0; i < 32; i += 8)
        tile[ty+i][tx] = in[(by+ty+i)*CH + bx+tx];
    __syncthreads();
    #pragma unroll
    for (int i = 0; i < 32; i += 8)
        out[(bx+ty+i)*CH + by+tx] = tile[tx][ty+i];
}

__global__ void zfill_kernel(float* __restrict__ p, int n)
{
    int i = blockIdx.x*blockDim.x + threadIdx.x;
    if (i < n) p[i] = 0.f;
}
__global__ void zinv_kernel(float* __restrict__ Z, int n)
{
    int i = blockIdx.x*blockDim.x + threadIdx.x;
    if (i < n) Z[i] = 1.0f / Z[i];
}

// ================= fp16 tensor-core GEMM =================
// C[M,N] = A*B (+bias).  !TRA: A[m,k] at A[m*lda+k];  TRA: A[m,k] at A[k*lda+m]
// BIAS: 0 none, 1 bias[row], 2 bias[col]
// EXPZ:  C elem -> half(exp2_fast(c*ESC)); row sums atomically added to Zp
// AHALF: A is __half in gmem (requires !TRA)
// BHALF: B is __half in gmem; BSCALE: scale B row k by zs[z*K+k]
// CHALF: store C as __half (non-EXPZ path)
// SPLITK>1: gridDim.y = SPLITK (M must fit one BM tile); fp32 atomicAdd epilogue
template<int BM, int BN, int WM, int WN, bool TRA, int BIAS, bool EXPZ,
         bool AHALF, bool BHALF, bool BSCALE, bool CHALF, int SPLITK>
__global__ void __launch_bounds__(256)
hgemm(const void* __restrict__ Av, const void* __restrict__ Bv,
      void* __restrict__ Cv, const float* __restrict__ bias,
      float* __restrict__ Zp, const float* __restrict__ zs_,
      int K, int lda, int ldb, int ldc, int zdiv,
      long long sA1, long long sA2, long long sB1, long long sB2,
      long long sC1, long long sC2)
{
    constexpr int BK = 32;
    constexpr int WCOLS = BN / WN;
    constexpr int MF = WM / 16;
    constexpr int NF = WN / 8;
    constexpr int PAD = 8;
    constexpr int AF_IT = AHALF ? 1 : (BM*BK)/(256*4);
    constexpr int AH_IT = AHALF ? (BM*BK)/(256*8) : 1;
    constexpr int BF_IT = BHALF ? 1 : (BK*BN)/(256*4);
    constexpr int BH_IT = BHALF ? (BK*BN)/(256*8) : 1;

    __shared__ __half As[2][BM][BK+PAD];
    __shared__ __half Bs[2][BK][BN+PAD];

    int z  = blockIdx.z;
    int z1 = z / zdiv, z2 = z - z1*zdiv;
    const float*  Af = AHALF ? nullptr : ((const float*)Av + z1*sA1 + z2*sA2);
    const __half* Ah = AHALF ? ((const __half*)Av + z1*sA1 + z2*sA2) : nullptr;
    const float*  Bf = BHALF ? nullptr : ((const float*)Bv + z1*sB1 + z2*sB2);
    const __half* Bh = BHALF ? ((const __half*)Bv + z1*sB1 + z2*sB2) : nullptr;
    float*  Cf = (EXPZ || CHALF) ? nullptr : ((float*)Cv + z1*sC1 + z2*sC2);
    __half* Ch = (EXPZ || CHALF) ? ((__half*)Cv + z1*sC1 + z2*sC2) : nullptr;
    const float* zs = BSCALE ? (zs_ + (long)z*K) : nullptr;

    int bm, kbase, Keff;
    if (SPLITK > 1){ bm = 0; kbase = blockIdx.y*(K/SPLITK); Keff = K/SPLITK; }
    else           { bm = blockIdx.y*BM; kbase = 0; Keff = K; }
    int bn = blockIdx.x*BN;

    int t    = threadIdx.x;
    int warp = t >> 5, lane = t & 31;
    int g = lane >> 2, t4 = lane & 3;
    int wy = warp / WCOLS, wx = warp % WCOLS;

    float4 raf[AF_IT];
    uint4  rah[AH_IT];
    float4 rbf[BF_IT];
    uint4  rbh[BH_IT];
    float  rbsc[BH_IT];

    auto gloadA = [&](int k0){
        if (AHALF){
            #pragma unroll
            for (int i = 0; i < AH_IT; i++){
                int idx = t + 256*i;
                int m = idx/(BK/8), k8 = idx%(BK/8);
                rah[i] = *reinterpret_cast<const uint4*>(&Ah[(long)(bm+m)*lda + k0 + k8*8]);
            }
        } else {
            #pragma unroll
            for (int i = 0; i < AF_IT; i++){
                int idx = t + 256*i;
                if (TRA){
                    int k = idx/(BM/4), m4 = idx%(BM/4);
                    raf[i] = *reinterpret_cast<const float4*>(&Af[(long)(k0+k)*lda + bm + m4*4]);
                } else {
                    int m = idx/(BK/4), k4 = idx%(BK/4);
                    raf[i] = *reinterpret_cast<const float4*>(&Af[(long)(bm+m)*lda + k0 + k4*4]);
                }
            }
        }
    };
    auto gloadB = [&](int k0){
        if (BHALF){
            #pragma unroll
            for (int i = 0; i < BH_IT; i++){
                int idx = t + 256*i;
                int k = idx/(BN/8), n8 = idx%(BN/8);
                rbh[i] = *reinterpret_cast<const uint4*>(&Bh[(long)(k0+k)*ldb + bn + n8*8]);
                if (BSCALE) rbsc[i] = zs[k0+k];
            }
        } else {
            #pragma unroll
            for (int i = 0; i < BF_IT; i++){
                int idx = t + 256*i;
                int k = idx/(BN/4), n4 = idx%(BN/4);
                rbf[i] = *reinterpret_cast<const float4*>(&Bf[(long)(k0+k)*ldb + bn + n4*4]);
            }
        }
    };
    auto stsA = [&](int s){
        if (AHALF){
            #pragma unroll
            for (int i = 0; i < AH_IT; i++){
                int idx = t + 256*i;
                int m = idx/(BK/8), k8 = idx%(BK/8);
                *reinterpret_cast<uint4*>(&As[s][m][k8*8]) = rah[i];
            }
        } else {
            #pragma unroll
            for (int i = 0; i < AF_IT; i++){
                int idx = t + 256*i;
                if (TRA){
                    int k = idx/(BM/4), m4 = idx%(BM/4);
                    As[s][m4*4+0][k] = __float2half_rn(raf[i].x);
                    As[s][m4*4+1][k] = __float2half_rn(raf[i].y);
                    As[s][m4*4+2][k] = __float2half_rn(raf[i].z);
                    As[s][m4*4+3][k] = __float2half_rn(raf[i].w);
                } else {
                    int m = idx/(BK/4), k4 = idx%(BK/4);
                    __half2 h01 = __floats2half2_rn(raf[i].x, raf[i].y);
                    __half2 h23 = __floats2half2_rn(raf[i].z, raf[i].w);
                    *reinterpret_cast<__half2*>(&As[s][m][k4*4  ]) = h01;
                    *reinterpret_cast<__half2*>(&As[s][m][k4*4+2]) = h23;
                }
            }
        }
    };
    auto stsB = [&](int s){
        if (BHALF){
            #pragma unroll
            for (int i = 0; i < BH_IT; i++){
                int idx = t + 256*i;
                int k = idx/(BN/8), n8 = idx%(BN/8);
                if (BSCALE){
                    const __half2* hp = reinterpret_cast<const __half2*>(&rbh[i]);
                    float sc = rbsc[i];
                    __half2 o[4];
                    #pragma unroll
                    for (int j = 0; j < 4; j++){
                        float2 f = __half22float2(hp[j]);
                        o[j] = __floats2half2_rn(f.x*sc, f.y*sc);
                    }
                    *reinterpret_cast<uint4*>(&Bs[s][k][n8*8]) = *reinterpret_cast<uint4*>(o);
                } else {
                    *reinterpret_cast<uint4*>(&Bs[s][k][n8*8]) = rbh[i];
                }
            }
        } else {
            #pragma unroll
            for (int i = 0; i < BF_IT; i++){
                int idx = t + 256*i;
                int k = idx/(BN/4), n4 = idx%(BN/4);
                __half2 h01 = __floats2half2_rn(rbf[i].x, rbf[i].y);
                __half2 h23 = __floats2half2_rn(rbf[i].z, rbf[i].w);
                *reinterpret_cast<__half2*>(&Bs[s][k][n4*4  ]) = h01;
                *reinterpret_cast<__half2*>(&Bs[s][k][n4*4+2]) = h23;
            }
        }
    };

    float acc[MF][NF][4] = {};

    gloadA(kbase); gloadB(kbase);
    stsA(0); stsB(0);
    __syncthreads();

    int nT = Keff / BK;
    for (int tI = 0; tI < nT; tI++){
        int cur = tI & 1, nxt = cur ^ 1;
        if (tI+1 < nT){ gloadA(kbase + (tI+1)*BK); gloadB(kbase + (tI+1)*BK); }

        int arow = wy*WM + (lane & 15);
        int acol = (lane >> 4) << 3;
        #pragma unroll
        for (int kc = 0; kc < BK/16; kc++){
            uint32_t af[MF][4]; uint32_t bf[NF][2];
            #pragma unroll
            for (int mf = 0; mf < MF; mf++){
                uint32_t a = smaddr(&As[cur][arow + mf*16][kc*16 + acol]);
                ldm_x4(af[mf][0], af[mf][1], af[mf][2], af[mf][3], a);
            }
            #pragma unroll
            for (int nf2 = 0; nf2 < NF/2; nf2++){
                uint32_t a = smaddr(&Bs[cur][kc*16 + (lane & 15)]
                                            [wx*WN + nf2*16 + ((lane >> 4) << 3)]);
                ldm_x4t(bf[nf2*2][0], bf[nf2*2][1], bf[nf2*2+1][0], bf[nf2*2+1][1], a);
            }
            #pragma unroll
            for (int mf = 0; mf < MF; mf++)
                #pragma unroll
                for (int nf = 0; nf < NF; nf++)
                    mma_f16(acc[mf][nf], af[mf], bf[nf]);
        }
        if (tI+1 < nT){ stsA(nxt); stsB(nxt); __syncthreads(); }
    }

    // ---------------- epilogue ----------------
    long zoff = EXPZ ? (long)z * ((long)gridDim.y * BM) : 0;
    #pragma unroll
    for (int mf = 0; mf < MF; mf++){
        int rbase = bm + wy*WM + mf*16 + g;
        #pragma unroll
        for (int half = 0; half < 2; half++){
            int r = rbase + half*8;
            float bM = (BIAS == 1) ? bias[r] : 0.f;
            float rowsum = 0.f;
            #pragma unroll
            for (int nf = 0; nf < NF; nf++){
                int cI = bn + wx*WN + nf*8 + t4*2;
                float v0 = acc[mf][nf][half*2 + 0];
                float v1 = acc[mf][nf][half*2 + 1];
                if (EXPZ){
                    v0 = exp2_fast(v0*ESC);
                    v1 = exp2_fast(v1*ESC);
                    rowsum += v0 + v1;
                    *reinterpret_cast<__half2*>(&Ch[(long)r*ldc + cI]) =
                        __floats2half2_rn(v0, v1);
                } else {
                    if (BIAS == 1){ v0 += bM; v1 += bM; }
                    if (BIAS == 2){ v0 += bias[cI]; v1 += bias[cI+1]; }
                    if (CHALF){
                        *reinterpret_cast<__half2*>(&Ch[(long)r*ldc + cI]) =
                            __floats2half2_rn(v0, v1);
                    } else if (SPLITK > 1){
                        atomicAdd(&Cf[(long)r*ldc + cI],     v0);
                        atomicAdd(&Cf[(long)r*ldc + cI + 1], v1);
                    } else {
                        *reinterpret_cast<float2*>(&Cf[(long)r*ldc + cI]) = make_float2(v0, v1);
                    }
                }
            }
            if (EXPZ){
                rowsum += __shfl_xor_sync(0xffffffffu, rowsum, 1);
                rowsum += __shfl_xor_sync(0xffffffffu, rowsum, 2);
                if (t4 == 0) atomicAdd(&Zp[zoff + r], rowsum);
            }
        }
    }
}

// ---------------- gating dot products ----------------
__global__ void gate_kernel(const float* __restrict__ gw, const float* __restrict__ gb)
{
    int i = blockIdx.x*blockDim.x + threadIdx.x;
    if (i >= BATCH*HW_N) return;
    int b = i / HW_N, m = i % HW_N;
    const float* xb = g_x2 + (long)b*CH*HW_N + m;
    const float* yb = g_y2 + (long)b*CH*HW_N + m;
    float s0 = gb[0], s1 = gb[1];
    for (int c = 0; c < CH; c++) {
        float xv = xb[(long)c*HW_N];
        s0 = fmaf(gw[c],      xv, s0);
        s1 = fmaf(gw[C2 + c], xv, s1);
    }
    for (int c = 0; c < CH; c++) {
        float yv = yb[(long)c*HW_N];
        s0 = fmaf(gw[CH + c],      yv, s0);
        s1 = fmaf(gw[C2 + CH + c], yv, s1);
    }
    g_gate[b*2*HW_N + m]        = 1.f + sigmoidf_(s0);
    g_gate[b*2*HW_N + HW_N + m] = 1.f + sigmoidf_(s1);
}

// ---------------- final gated writeback ----------------
__global__ void final_kernel(float* __restrict__ out)
{
    long i = (long)blockIdx.x*blockDim.x + threadIdx.x;
    if (i >= (long)BATCH*CH*HW_N) return;
    int b = (int)(i / (CH*HW_N));
    int m = (int)(i % HW_N);
    out[i]                       = g_x2[i] * g_gate[b*2*HW_N + m];
    out[(long)BATCH*CH*HW_N + i] = g_y2[i] * g_gate[b*2*HW_N + HW_N + m];
}

// ---------------- host orchestration ----------------
extern "C" void kernel_launch(void* const* d_in, const int* in_sizes, int n_in,
                              void* d_out, int out_size)
{
    const float* x      = (const float*)d_in[0];
    const float* y      = (const float*)d_in[1];
    const float* fc1w   = (const float*)d_in[2];
    const float* fc1b   = (const float*)d_in[3];
    const float* fc2w   = (const float*)d_in[4];
    const float* fc2b   = (const float*)d_in[5];
    const float* t1_qw  = (const float*)d_in[6];
    const float* t1_qb  = (const float*)d_in[7];
    const float* t1_kw  = (const float*)d_in[8];
    const float* t1_kb  = (const float*)d_in[9];
    const float* t1_vw  = (const float*)d_in[10];
    const float* t1_vb  = (const float*)d_in[11];
    const float* t2_qw  = (const float*)d_in[12];
    const float* t2_qb  = (const float*)d_in[13];
    const float* t2_kw  = (const float*)d_in[14];
    const float* t2_kb  = (const float*)d_in[15];
    const float* t2_vw  = (const float*)d_in[16];
    const float* t2_vb  = (const float*)d_in[17];
    const float* gate_w = (const float*)d_in[18];
    const float* gate_b = (const float*)d_in[19];

    float *xs, *ys, *x2, *y2, *Z, *wt1, *wt2;
    __half *q, *k, *v, *S;
    cudaGetSymbolAddress((void**)&xs,  g_xs);
    cudaGetSymbolAddress((void**)&ys,  g_ys);
    cudaGetSymbolAddress((void**)&q,   g_q);
    cudaGetSymbolAddress((void**)&k,   g_k);
    cudaGetSymbolAddress((void**)&v,   g_v);
    cudaGetSymbolAddress((void**)&S,   g_S);
    cudaGetSymbolAddress((void**)&x2,  g_x2);
    cudaGetSymbolAddress((void**)&y2,  g_y2);
    cudaGetSymbolAddress((void**)&Z,   g_Z);
    cudaGetSymbolAddress((void**)&wt1, g_wt1);
    cudaGetSymbolAddress((void**)&wt2, g_wt2);

    const long total = (long)BATCH*CH*HW_N;
    const long long NN  = (long long)HW_N*HW_N;
    const long long CN  = (long long)CH*HW_N;
    const long long HN  = (long long)DK*HW_N;
    const int ZROWS = BATCH*NH*HW_N;

    // --- prologue: RScaling + weight transposes (capture slot 5 = q-conv) ---
    pool_kernel<<<BATCH*C2, 256>>>(x, y);                               // 1
    se_kernel<<<BATCH, C2>>>(fc1w, fc1b, fc2w, fc2b);                   // 2
    scale_kernel<<<(int)((total + 255)/256), 256>>>(x, y);              // 3
    transpose256x2<<<dim3(8,8,2), dim3(32,8)>>>(t1_qw, wt1, t2_qw, wt2);// 4

    auto rtrans = [&](const float* qin, const float* kvin,
                      const float* wtq, const float* qb,
                      const float* kw, const float* kb,
                      const float* vw, const float* vb, float* outp)
    {
        // q_t[b][n][c] (half) = sum_c' qin[b][c'][n] * wtq[c'][c] + qb[c]
        hgemm<128,128,64,32, true,2,false, false,false,false, true,1>
            <<<dim3(CH/128, HW_N/128, BATCH), 256>>>(
            qin, wtq, q, qb, nullptr, nullptr,
            CH, HW_N, CH, CH,
            1, CN, 0, 0, 0, CN, 0);
        // k[b][o][m] (half) = sum_c kw[o][c]*kvin[b][c][m] + kb[o]
        hgemm<64,128,32,32, false,1,false, false,false,false, true,1>
            <<<dim3(HW_N/128, CH/64, BATCH), 256>>>(
            kw, kvin, k, kb, nullptr, nullptr,
            CH, CH, HW_N, HW_N,
            1, 0, 0, CN, 0, CN, 0);
        hgemm<64,128,32,32, false,1,false, false,false,false, true,1>
            <<<dim3(HW_N/128, CH/64, BATCH), 256>>>(
            vw, kvin, v, vb, nullptr, nullptr,
            CH, CH, HW_N, HW_N,
            1, 0, 0, CN, 0, CN, 0);
        // zero row sums
        zfill_kernel<<<(ZROWS + 255)/256, 256>>>(Z, ZROWS);
        // E[z][n][m] = half(exp2(S*ESC)); Z[z][n] += row sums (atomic)
        hgemm<128,128,64,32, false,0,true, true,true,false, false,1>
            <<<dim3(HW_N/128, HW_N/128, BATCH*NH), 256>>>(
            q, k, S, nullptr, Z, nullptr,
            DK, CH, HW_N, HW_N,
            NH, (long long)HW_N*CH, DK, CN, HN, (long long)NH*NN, NN);
        zinv_kernel<<<(ZROWS + 255)/256, 256>>>(Z, ZROWS);
        // zero output, then split-K PV with fp32 atomic accumulation
        zfill_kernel<<<(int)((total + 255)/256), 256>>>(outp, (int)total);
        hgemm<64,128,32,32, false,0,false, true,true,true, false,3>
            <<<dim3(HW_N/128, 3, BATCH*NH), 256>>>(
            v, S, outp, nullptr, nullptr, Z,
            HW_N, HW_N, HW_N, HW_N,
            NH, CN, HN, (long long)NH*NN, NN, CN, HN);
    };

    // RTrans 1: x = attn(q=xs, k=ys, v=ys)
    rtrans(xs, ys, wt1, t1_qb, t1_kw, t1_kb, t1_vw, t1_vb, x2);
    // RTrans 2: y = attn(q=ys, k=x2, v=x2)
    rtrans(ys, x2, wt2, t2_qb, t2_kw, t2_kb, t2_vw, t2_vb, y2);

    // --- RGating + final writeback ---
    gate_kernel<<<(BATCH*HW_N + 255)/256, 256>>>(gate_w, gate_b);
    final_kernel<<<(int)((total + 255)/256), 256>>>((float*)d_out);
}

// round 6
// speedup vs baseline: 3.9139x; 1.1320x over previous
#include <cuda_runtime.h>
#include <cuda_fp16.h>
#include <math.h>
#include <stdint.h>

// ---------------- problem constants ----------------
#define BATCH 2
#define CH    256
#define NH    4
#define DK    64          // CH / NH
#define HW_N  2304        // 48*48
#define C2    512         // 2*CH

#define ESC 0.18033688011112042f   // 0.125 * log2(e)

// ---------------- scratch (device globals) ----------
__device__ __half g_xs[BATCH*CH*HW_N];
__device__ __half g_ys[BATCH*CH*HW_N];
__device__ __half g_q [BATCH*CH*HW_N];            // [b][n][c]
__device__ __half g_kv[BATCH*C2*HW_N];            // rows 0-255 = k, 256-511 = v  [b][c][n]
__device__ float  g_x2[BATCH*CH*HW_N];
__device__ float  g_y2[BATCH*CH*HW_N];
__device__ __half g_x2h[BATCH*CH*HW_N];
__device__ __half g_S [(size_t)BATCH*NH*HW_N*HW_N]; // 85 MB: E = exp(S*0.125)
__device__ float  g_Z [BATCH*NH*HW_N];
__device__ __half g_wt1h[CH*CH];                  // t1_qw transposed, half
__device__ __half g_wt2h[CH*CH];
__device__ __half g_wkv1[C2*CH];                  // packed [kw; vw] half
__device__ __half g_wkv2[C2*CH];
__device__ float  g_kvb1[C2];
__device__ float  g_kvb2[C2];
__device__ float  g_pooled[BATCH*C2];
__device__ float  g_sescale[BATCH*C2];
__device__ float  g_gate[BATCH*2*HW_N];

__device__ __forceinline__ float sigmoidf_(float v){ return 1.f/(1.f+expf(-v)); }

__device__ __forceinline__ float exp2_fast(float x)
{
    x = fminf(fmaxf(x, -60.f), 60.f);
    float m  = x + 12582912.0f;
    float rn = m - 12582912.0f;
    float r  = x - rn;
    int   iv = __float_as_int(m) - 0x4B400000;
    float p  = 0.0096181291f;
    p = fmaf(p, r, 0.0555041086f);
    p = fmaf(p, r, 0.2402265069f);
    p = fmaf(p, r, 0.6931471806f);
    p = fmaf(p, r, 1.0f);
    return p * __int_as_float((iv + 127) << 23);
}

__device__ __forceinline__ uint32_t smaddr(const void* p){
    return (uint32_t)__cvta_generic_to_shared(p);
}
__device__ __forceinline__ void cpa16(uint32_t dst, const void* src){
    asm volatile("cp.async.cg.shared.global [%0], [%1], 16;" :: "r"(dst), "l"(src));
}
__device__ __forceinline__ void cpa_commit(){
    asm volatile("cp.async.commit_group;" ::: "memory");
}
__device__ __forceinline__ void ldm_x4(uint32_t &r0, uint32_t &r1, uint32_t &r2, uint32_t &r3,
                                       uint32_t a){
    asm volatile("ldmatrix.sync.aligned.m8n8.x4.shared.b16 {%0,%1,%2,%3}, [%4];"
        : "=r"(r0),"=r"(r1),"=r"(r2),"=r"(r3) : "r"(a));
}
__device__ __forceinline__ void ldm_x4t(uint32_t &r0, uint32_t &r1, uint32_t &r2, uint32_t &r3,
                                        uint32_t a){
    asm volatile("ldmatrix.sync.aligned.m8n8.x4.trans.shared.b16 {%0,%1,%2,%3}, [%4];"
        : "=r"(r0),"=r"(r1),"=r"(r2),"=r"(r3) : "r"(a));
}
__device__ __forceinline__ void mma_f16(float (&c)[4], uint32_t a0, uint32_t a1,
                                        uint32_t a2, uint32_t a3,
                                        uint32_t b0, uint32_t b1)
{
    asm volatile("mma.sync.aligned.m16n8k16.row.col.f32.f16.f16.f32 "
        "{%0,%1,%2,%3}, {%4,%5,%6,%7}, {%8,%9}, {%0,%1,%2,%3};"
        : "+f"(c[0]), "+f"(c[1]), "+f"(c[2]), "+f"(c[3])
        : "r"(a0), "r"(a1), "r"(a2), "r"(a3), "r"(b0), "r"(b1));
}

// ---------------- small kernels ----------------
__global__ void pool_kernel(const float* __restrict__ x, const float* __restrict__ y)
{
    int idx = blockIdx.x;
    int b = idx / C2, ch = idx % C2;
    const float* src = (ch < CH) ? (x + ((long)b*CH + ch)*HW_N)
                                 : (y + ((long)b*CH + (ch-CH))*HW_N);
    float s = 0.f;
    for (int i = threadIdx.x; i < HW_N; i += 256) s += src[i];
    __shared__ float red[256];
    red[threadIdx.x] = s; __syncthreads();
    for (int st = 128; st > 0; st >>= 1) {
        if (threadIdx.x < st) red[threadIdx.x] += red[threadIdx.x+st];
        __syncthreads();
    }
    if (threadIdx.x == 0) g_pooled[idx] = red[0] / (float)HW_N;
}

__global__ void se_kernel(const float* __restrict__ w1, const float* __restrict__ b1,
                          const float* __restrict__ w2, const float* __restrict__ b2)
{
    int b = blockIdx.x, t = threadIdx.x;   // 512 threads
    __shared__ float sp[C2], sh[DK];
    sp[t] = g_pooled[b*C2 + t];
    __syncthreads();
    if (t < DK) {
        float s = b1[t];
        for (int c = 0; c < C2; c++) s += w1[t*C2 + c] * sp[c];
        sh[t] = fmaxf(s, 0.f);
    }
    __syncthreads();
    float f = b2[t];
    for (int j = 0; j < DK; j++) f += w2[t*DK + j] * sh[j];
    g_sescale[b*C2 + t] = 1.f + sigmoidf_(f);
}

__global__ void scale_kernel(const float* __restrict__ x, const float* __restrict__ y)
{
    long i = (long)blockIdx.x*blockDim.x + threadIdx.x;
    if (i >= (long)BATCH*CH*HW_N) return;
    int b = (int)(i / (CH*HW_N));
    int c = (int)((i / HW_N) % CH);
    g_xs[i] = __float2half_rn(x[i] * g_sescale[b*C2 + c]);
    g_ys[i] = __float2half_rn(y[i] * g_sescale[b*C2 + CH + c]);
}

// transpose q weights -> half
__global__ void transpose256x2(const float* __restrict__ in0, __half* __restrict__ out0,
                               const float* __restrict__ in1, __half* __restrict__ out1)
{
    const float* in  = blockIdx.z ? in1  : in0;
    __half*      out = blockIdx.z ? out1 : out0;
    __shared__ float tile[32][33];
    int bx = blockIdx.x*32, by = blockIdx.y*32;
    int tx = threadIdx.x, ty = threadIdx.y;
    #pragma unroll
    for (int i = 0; i < 32; i += 8)
        tile[ty+i][tx] = in[(by+ty+i)*CH + bx+tx];
    __syncthreads();
    #pragma unroll
    for (int i = 0; i < 32; i += 8)
        out[(bx+ty+i)*CH + by+tx] = __float2half_rn(tile[tx][ty+i]);
}

// pack k/v weights+biases -> half (both rtrans)
__global__ void wpack_kernel(const float* __restrict__ kw1, const float* __restrict__ vw1,
                             const float* __restrict__ kb1, const float* __restrict__ vb1,
                             const float* __restrict__ kw2, const float* __restrict__ vw2,
                             const float* __restrict__ kb2, const float* __restrict__ vb2)
{
    int i = blockIdx.x*blockDim.x + threadIdx.x;   // over 2*C2*CH
    if (i >= 2*C2*CH) return;
    int which = i / (C2*CH);
    int idx = i % (C2*CH);
    int row = idx / CH, col = idx % CH;
    const float* kw = which ? kw2 : kw1;
    const float* vw = which ? vw2 : vw1;
    __half* dst = which ? g_wkv2 : g_wkv1;
    dst[idx] = __float2half_rn(row < CH ? kw[row*CH + col] : vw[(row-CH)*CH + col]);
    if (idx < C2){
        const float* kb = which ? kb2 : kb1;
        const float* vb = which ? vb2 : vb1;
        float* db = which ? g_kvb2 : g_kvb1;
        db[idx] = (idx < CH) ? kb[idx] : vb[idx-CH];
    }
}

__global__ void zfill_kernel(float* __restrict__ p, int n)
{
    int i = blockIdx.x*blockDim.x + threadIdx.x;
    if (i < n) p[i] = 0.f;
}
__global__ void zinv_kernel(float* __restrict__ Z, int n)
{
    int i = blockIdx.x*blockDim.x + threadIdx.x;
    if (i < n) Z[i] = 1.0f / Z[i];
}

// scale v rows (g_kv rows 256..511) by invZ[(b,h,n)]
__global__ void vscale_kernel()
{
    long i = (long)blockIdx.x*blockDim.x + threadIdx.x;
    if (i >= (long)BATCH*CH*HW_N) return;
    int b = (int)(i / (CH*HW_N));
    int c = (int)((i / HW_N) % CH);
    int n = (int)(i % HW_N);
    long off = ((long)b*C2 + CH + c)*HW_N + n;
    float z = g_Z[((long)b*NH + (c >> 6))*HW_N + n];
    g_kv[off] = __float2half_rn(__half2float(g_kv[off]) * z);
}

// fp32 -> half copy
__global__ void f2h_kernel(const float* __restrict__ src, __half* __restrict__ dst, int n)
{
    int i = blockIdx.x*blockDim.x + threadIdx.x;
    if (i < n) dst[i] = __float2half_rn(src[i]);
}

// ================= all-half cp.async 3-stage tensor-core GEMM =================
// C[M,N] = A*B (+bias).
// !TRA: A[m,k] at A[m*lda+k] (smem [m][k], ldmatrix non-trans)
//  TRA: A[m,k] at A[k*lda+m] (smem [k][m], ldmatrix.trans + fragment swap)
// BIAS: 0 none, 1 bias[row], 2 bias[col]
// EXPZ: C elem -> half(exp2_fast(c*ESC)); row sums atomically added to Zp[z*2304+row]
// CHALF: store C half; else float (SPLITK>1: atomicAdd)
template<int BM, int BN, int WM, int WN, bool TRA, int BIAS, bool EXPZ, bool CHALF, int SPLITK>
__global__ void __launch_bounds__(256)
hgemm(const __half* __restrict__ A, const __half* __restrict__ B,
      void* __restrict__ Cv, const float* __restrict__ bias,
      float* __restrict__ Zp,
      int K, int lda, int ldb, int ldc, int zdiv,
      long long sA1, long long sA2, long long sB1, long long sB2,
      long long sC1, long long sC2)
{
    constexpr int BK = 32;
    constexpr int ST = 3;
    constexpr int WCOLS = BN / WN;
    constexpr int MF = WM / 16;
    constexpr int NF = WN / 8;
    constexpr int PAD = 8;
    constexpr int A_CH = (BM*BK/8)/256;   // 16B chunks per thread
    constexpr int B_CH = (BK*BN/8)/256;

    __shared__ __half As[ST][TRA ? BK : BM][(TRA ? BM : BK) + PAD];
    __shared__ __half Bs[ST][BK][BN + PAD];

    int z  = blockIdx.z;
    int z1 = z / zdiv, z2 = z - z1*zdiv;
    A += z1*sA1 + z2*sA2;
    B += z1*sB1 + z2*sB2;
    float*  Cf = (EXPZ || CHALF) ? nullptr : ((float*)Cv + z1*sC1 + z2*sC2);
    __half* Ch = (EXPZ || CHALF) ? ((__half*)Cv + z1*sC1 + z2*sC2) : nullptr;

    int bm, kbase, Keff;
    if (SPLITK > 1){ bm = 0; kbase = blockIdx.y*(K/SPLITK); Keff = K/SPLITK; }
    else           { bm = blockIdx.y*BM; kbase = 0; Keff = K; }
    int bn = blockIdx.x*BN;

    int t    = threadIdx.x;
    int warp = t >> 5, lane = t & 31;
    int g = lane >> 2, t4 = lane & 3;
    int wy = warp / WCOLS, wx = warp % WCOLS;

    auto issue = [&](int s, int k0){
        #pragma unroll
        for (int i = 0; i < A_CH; i++){
            int idx = t + 256*i;
            if (TRA){
                int k = idx/(BM/8), m8 = idx%(BM/8);
                cpa16(smaddr(&As[s][k][m8*8]), &A[(long)(k0+k)*lda + bm + m8*8]);
            } else {
                int m = idx/(BK/8), k8 = idx%(BK/8);
                cpa16(smaddr(&As[s][m][k8*8]), &A[(long)(bm+m)*lda + k0 + k8*8]);
            }
        }
        #pragma unroll
        for (int i = 0; i < B_CH; i++){
            int idx = t + 256*i;
            int k = idx/(BN/8), n8 = idx%(BN/8);
            cpa16(smaddr(&Bs[s][k][n8*8]), &B[(long)(k0+k)*ldb + bn + n8*8]);
        }
        cpa_commit();
    };

    float acc[MF][NF][4] = {};

    int nT = Keff / BK;
    issue(0, kbase);
    if (nT > 1) issue(1, kbase + BK);

    for (int tI = 0; tI < nT; tI++){
        if (tI < nT-1) asm volatile("cp.async.wait_group 1;" ::: "memory");
        else           asm volatile("cp.async.wait_group 0;" ::: "memory");
        __syncthreads();
        if (tI + 2 < nT) issue((tI+2)%ST, kbase + (tI+2)*BK);

        int cur = tI % ST;
        #pragma unroll
        for (int kc = 0; kc < BK/16; kc++){
            uint32_t af[MF][4]; uint32_t bf[NF][2];
            #pragma unroll
            for (int mf = 0; mf < MF; mf++){
                if (TRA){
                    uint32_t r0,r1,r2,r3;
                    uint32_t a = smaddr(&As[cur][kc*16 + (lane & 15)]
                                                [wy*WM + mf*16 + ((lane >> 4) << 3)]);
                    ldm_x4t(r0, r1, r2, r3, a);
                    af[mf][0]=r0; af[mf][1]=r2; af[mf][2]=r1; af[mf][3]=r3;
                } else {
                    uint32_t a = smaddr(&As[cur][wy*WM + mf*16 + (lane & 15)]
                                                [kc*16 + ((lane >> 4) << 3)]);
                    ldm_x4(af[mf][0], af[mf][1], af[mf][2], af[mf][3], a);
                }
            }
            #pragma unroll
            for (int nf2 = 0; nf2 < NF/2; nf2++){
                uint32_t a = smaddr(&Bs[cur][kc*16 + (lane & 15)]
                                            [wx*WN + nf2*16 + ((lane >> 4) << 3)]);
                ldm_x4t(bf[nf2*2][0], bf[nf2*2][1], bf[nf2*2+1][0], bf[nf2*2+1][1], a);
            }
            #pragma unroll
            for (int mf = 0; mf < MF; mf++)
                #pragma unroll
                for (int nf = 0; nf < NF; nf++)
                    mma_f16(acc[mf][nf], af[mf][0], af[mf][1], af[mf][2], af[mf][3],
                            bf[nf][0], bf[nf][1]);
        }
    }

    // ---------------- epilogue ----------------
    long zoff = EXPZ ? (long)z * (long)HW_N : 0;
    #pragma unroll
    for (int mf = 0; mf < MF; mf++){
        int rbase = bm + wy*WM + mf*16 + g;
        #pragma unroll
        for (int half = 0; half < 2; half++){
            int r = rbase + half*8;
            float bM = (BIAS == 1) ? bias[r] : 0.f;
            float rowsum = 0.f;
            #pragma unroll
            for (int nf = 0; nf < NF; nf++){
                int cI = bn + wx*WN + nf*8 + t4*2;
                float v0 = acc[mf][nf][half*2 + 0];
                float v1 = acc[mf][nf][half*2 + 1];
                if (EXPZ){
                    v0 = exp2_fast(v0*ESC);
                    v1 = exp2_fast(v1*ESC);
                    rowsum += v0 + v1;
                    *reinterpret_cast<__half2*>(&Ch[(long)r*ldc + cI]) =
                        __floats2half2_rn(v0, v1);
                } else {
                    if (BIAS == 1){ v0 += bM; v1 += bM; }
                    if (BIAS == 2){ v0 += bias[cI]; v1 += bias[cI+1]; }
                    if (CHALF){
                        *reinterpret_cast<__half2*>(&Ch[(long)r*ldc + cI]) =
                            __floats2half2_rn(v0, v1);
                    } else if (SPLITK > 1){
                        atomicAdd(&Cf[(long)r*ldc + cI],     v0);
                        atomicAdd(&Cf[(long)r*ldc + cI + 1], v1);
                    } else {
                        *reinterpret_cast<float2*>(&Cf[(long)r*ldc + cI]) = make_float2(v0, v1);
                    }
                }
            }
            if (EXPZ){
                rowsum += __shfl_xor_sync(0xffffffffu, rowsum, 1);
                rowsum += __shfl_xor_sync(0xffffffffu, rowsum, 2);
                if (t4 == 0) atomicAdd(&Zp[zoff + r], rowsum);
            }
        }
    }
}

// ---------------- gating dot products ----------------
__global__ void gate_kernel(const float* __restrict__ gw, const float* __restrict__ gb)
{
    int i = blockIdx.x*blockDim.x + threadIdx.x;
    if (i >= BATCH*HW_N) return;
    int b = i / HW_N, m = i % HW_N;
    const float* xb = g_x2 + (long)b*CH*HW_N + m;
    const float* yb = g_y2 + (long)b*CH*HW_N + m;
    float s0 = gb[0], s1 = gb[1];
    for (int c = 0; c < CH; c++) {
        float xv = xb[(long)c*HW_N];
        s0 = fmaf(gw[c],      xv, s0);
        s1 = fmaf(gw[C2 + c], xv, s1);
    }
    for (int c = 0; c < CH; c++) {
        float yv = yb[(long)c*HW_N];
        s0 = fmaf(gw[CH + c],      yv, s0);
        s1 = fmaf(gw[C2 + CH + c], yv, s1);
    }
    g_gate[b*2*HW_N + m]        = 1.f + sigmoidf_(s0);
    g_gate[b*2*HW_N + HW_N + m] = 1.f + sigmoidf_(s1);
}

__global__ void final_kernel(float* __restrict__ out)
{
    long i = (long)blockIdx.x*blockDim.x + threadIdx.x;
    if (i >= (long)BATCH*CH*HW_N) return;
    int b = (int)(i / (CH*HW_N));
    int m = (int)(i % HW_N);
    out[i]                       = g_x2[i] * g_gate[b*2*HW_N + m];
    out[(long)BATCH*CH*HW_N + i] = g_y2[i] * g_gate[b*2*HW_N + HW_N + m];
}

// ---------------- host orchestration ----------------
extern "C" void kernel_launch(void* const* d_in, const int* in_sizes, int n_in,
                              void* d_out, int out_size)
{
    const float* x      = (const float*)d_in[0];
    const float* y      = (const float*)d_in[1];
    const float* fc1w   = (const float*)d_in[2];
    const float* fc1b   = (const float*)d_in[3];
    const float* fc2w   = (const float*)d_in[4];
    const float* fc2b   = (const float*)d_in[5];
    const float* t1_qw  = (const float*)d_in[6];
    const float* t1_qb  = (const float*)d_in[7];
    const float* t1_kw  = (const float*)d_in[8];
    const float* t1_kb  = (const float*)d_in[9];
    const float* t1_vw  = (const float*)d_in[10];
    const float* t1_vb  = (const float*)d_in[11];
    const float* t2_qw  = (const float*)d_in[12];
    const float* t2_qb  = (const float*)d_in[13];
    const float* t2_kw  = (const float*)d_in[14];
    const float* t2_kb  = (const float*)d_in[15];
    const float* t2_vw  = (const float*)d_in[16];
    const float* t2_vb  = (const float*)d_in[17];
    const float* gate_w = (const float*)d_in[18];
    const float* gate_b = (const float*)d_in[19];

    float *x2, *y2, *Z, *kvb1, *kvb2;
    __half *xs, *ys, *q, *kv, *S, *x2h, *wt1h, *wt2h, *wkv1, *wkv2;
    cudaGetSymbolAddress((void**)&xs,   g_xs);
    cudaGetSymbolAddress((void**)&ys,   g_ys);
    cudaGetSymbolAddress((void**)&q,    g_q);
    cudaGetSymbolAddress((void**)&kv,   g_kv);
    cudaGetSymbolAddress((void**)&S,    g_S);
    cudaGetSymbolAddress((void**)&x2,   g_x2);
    cudaGetSymbolAddress((void**)&y2,   g_y2);
    cudaGetSymbolAddress((void**)&x2h,  g_x2h);
    cudaGetSymbolAddress((void**)&Z,    g_Z);
    cudaGetSymbolAddress((void**)&wt1h, g_wt1h);
    cudaGetSymbolAddress((void**)&wt2h, g_wt2h);
    cudaGetSymbolAddress((void**)&wkv1, g_wkv1);
    cudaGetSymbolAddress((void**)&wkv2, g_wkv2);
    cudaGetSymbolAddress((void**)&kvb1, g_kvb1);
    cudaGetSymbolAddress((void**)&kvb2, g_kvb2);

    const long total = (long)BATCH*CH*HW_N;
    const long long NN  = (long long)HW_N*HW_N;
    const long long CN  = (long long)CH*HW_N;
    const long long HN  = (long long)DK*HW_N;
    const int ZROWS = BATCH*NH*HW_N;

    // --- prologue ---
    pool_kernel<<<BATCH*C2, 256>>>(x, y);
    se_kernel<<<BATCH, C2>>>(fc1w, fc1b, fc2w, fc2b);
    scale_kernel<<<(int)((total + 255)/256), 256>>>(x, y);
    transpose256x2<<<dim3(8,8,2), dim3(32,8)>>>(t1_qw, wt1h, t2_qw, wt2h);
    wpack_kernel<<<(2*C2*CH + 255)/256, 256>>>(t1_kw, t1_vw, t1_kb, t1_vb,
                                               t2_kw, t2_vw, t2_kb, t2_vb);

    auto rtrans = [&](const __half* qin, const __half* kvin,
                      const __half* wtq, const float* qb,
                      const __half* wkv, const float* kvb, float* outp)
    {
        // q_t[b][n][c] = sum_c' qin[b][c'][n] * wtq[c'][c] + qb[c]   (TRA, col bias)
        hgemm<128,64,32,32, true,2,false,true,1>
            <<<dim3(CH/64, HW_N/128, BATCH), 256>>>(
            qin, wtq, q, qb, nullptr,
            CH, HW_N, CH, CH,
            1, CN, 0, 0, 0, CN, 0);
        // kv[b][o][n] = sum_c wkv[o][c]*kvin[b][c][n] + kvb[o]   (o in 0..511)
        hgemm<128,128,64,32, false,1,false,true,1>
            <<<dim3(HW_N/128, C2/128, BATCH), 256>>>(
            wkv, kvin, kv, kvb, nullptr,
            CH, CH, HW_N, HW_N,
            1, 0, 0, CN, 0, (long long)C2*HW_N, 0);
        // row sums
        zfill_kernel<<<(ZROWS + 255)/256, 256>>>(Z, ZROWS);
        // E[z][n][m] = half(exp2(S*ESC)); Z[z][n] += rowsums
        hgemm<128,128,64,32, false,0,true,false,1>
            <<<dim3(HW_N/128, HW_N/128, BATCH*NH), 256>>>(
            q, kv, S, nullptr, Z,
            DK, CH, HW_N, HW_N,
            NH, (long long)HW_N*CH, DK, (long long)C2*HW_N, HN,
            (long long)NH*NN, NN);
        zinv_kernel<<<(ZROWS + 255)/256, 256>>>(Z, ZROWS);
        // v *= invZ  (rows 256..511 of g_kv)
        vscale_kernel<<<(int)((total + 255)/256), 256>>>();
        // out[b][h*64+d][m] = sum_n vZ[d][n] * E[z][n][m]   (split-K=3, fp32 atomics)
        zfill_kernel<<<(int)((total + 255)/256), 256>>>(outp, (int)total);
        hgemm<64,128,32,32, false,0,false,false,3>
            <<<dim3(HW_N/128, 3, BATCH*NH), 256>>>(
            kv + (long)CH*HW_N, S, outp, nullptr, nullptr,
            HW_N, HW_N, HW_N, HW_N,
            NH, (long long)C2*HW_N, HN, (long long)NH*NN, NN, CN, HN);
    };

    // RTrans 1: x = attn(q=xs, k=ys, v=ys)
    rtrans(xs, ys, wt1h, t1_qb, wkv1, kvb1, x2);
    // x2 -> half for rtrans2 conv inputs
    f2h_kernel<<<(int)((total + 255)/256), 256>>>(x2, x2h, (int)total);
    // RTrans 2: y = attn(q=ys, k=x2, v=x2)
    rtrans(ys, x2h, wt2h, t2_qb, wkv2, kvb2, y2);

    // --- RGating + final writeback ---
    gate_kernel<<<(BATCH*HW_N + 255)/256, 256>>>(gate_w, gate_b);
    final_kernel<<<(int)((total + 255)/256), 256>>>((float*)d_out);
}